// round 4
// baseline (speedup 1.0000x reference)
#include <cuda_runtime.h>

#define BB 32
#define NN 128
#define DD 135
#define OBS 7
#define FF 64
#define ADJ_OFF 7

// ---------------- device global scratch (allocation-free) ----------------
__device__ float g_norm[BB * NN];
__device__ float g_ee[BB * NN * FF];
__device__ float g_curA[BB * NN * FF];
__device__ float g_curB[BB * NN * FF];
__device__ float g_PQ[BB * NN * 8];
__device__ float g_Abias[BB * 4];
__device__ float g_Wt[6 * 128 * 64];   // transposed W_msg/W_upd: [l*2+s][k][f]

// ---------------- K0: transpose layer weights once -------------------------
__global__ void k_wt(const float* __restrict__ Wm, const float* __restrict__ Wu) {
    int m = blockIdx.x;                     // 0..5
    const float* src = (m & 1) ? (Wu + (m >> 1) * 8192) : (Wm + (m >> 1) * 8192);
    float* dst = g_Wt + m * 8192;
    for (int i = threadIdx.x; i < 8192; i += 256) {
        int f = i >> 7, k = i & 127;        // src[f][k] row-major (64,128)
        dst[k * 64 + f] = src[i];
    }
}

// ---------------- K1: norm per column (coalesced) --------------------------
__global__ void k_norm(const float* __restrict__ obs) {
    __shared__ float part[4][128];
    int b = blockIdx.x, t = threadIdx.x;
    int q = t >> 5, l = t & 31;             // 4 row-strips x 32 lanes
    const float* o = obs + b * (NN * DD) + ADJ_OFF;
    float c0 = 0.f, c1 = 0.f, c2 = 0.f, c3 = 0.f;
#pragma unroll 4
    for (int i = q * 32; i < q * 32 + 32; i++) {
        const float* row = o + i * DD;
        c0 += (row[l]      != 0.0f) ? 1.0f : 0.0f;
        c1 += (row[l + 32] != 0.0f) ? 1.0f : 0.0f;
        c2 += (row[l + 64] != 0.0f) ? 1.0f : 0.0f;
        c3 += (row[l + 96] != 0.0f) ? 1.0f : 0.0f;
    }
    part[q][l] = c0; part[q][l + 32] = c1;
    part[q][l + 64] = c2; part[q][l + 96] = c3;
    __syncthreads();
    if (t < 128) {
        float s = part[0][t] + part[1][t] + part[2][t] + part[3][t];
        g_norm[b * NN + t] = (s == 0.0f) ? 1.0f : s;
    }
}

// ---------------- K2: edge stage + init embedding --------------------------
#define EDGE_SMEM_FLOATS (1024 + 512 + 512 + 64*65 + 8192 + 16*129 + 1024 + 128 + 256)
__global__ void k_edge(const float* __restrict__ obs,
                       const float* __restrict__ W_init,
                       const float* __restrict__ W_ee,
                       const float* __restrict__ W_ef) {
    extern __shared__ float sm[];
    float* s_nf   = sm;
    float* s_wee  = s_nf + 1024;
    float* s_wi   = s_wee + 512;
    float* s_weft = s_wi + 512;
    float* s_c    = s_weft + 64 * 65;
    float* s_adj  = s_c + 8192;
    float* s_es   = s_adj + 16 * 129;
    float* s_nm   = s_es + 1024;
    float* s_red  = s_nm + 128;

    int b = blockIdx.x >> 3;
    int r0 = (blockIdx.x & 7) << 4;
    int t = threadIdx.x;
    const float* ob = obs + b * NN * DD;

    for (int idx = t; idx < NN * OBS; idx += 256) {
        int j = idx / OBS, d = idx - j * OBS;
        s_nf[j * 8 + d] = ob[j * DD + d];
    }
    for (int idx = t; idx < 512; idx += 256)
        s_wee[idx] = (idx < 63 * 8) ? W_ee[idx] : 0.0f;
    for (int idx = t; idx < 512; idx += 256) {
        int f = idx >> 3, d = idx & 7;
        s_wi[idx] = (d < 7) ? W_init[f * 7 + d] : 0.0f;
    }
    for (int idx = t; idx < 4096; idx += 256) {
        int f = idx >> 6, k = idx & 63;
        s_weft[k * 65 + f] = W_ef[idx];
    }
    for (int idx = t; idx < 16 * NN; idx += 256) {
        int r = idx >> 7, j = idx & 127;
        s_adj[r * 129 + j] = ob[(r0 + r) * DD + ADJ_OFF + j];
    }
    for (int idx = t; idx < NN; idx += 256) s_nm[idx] = g_norm[b * NN + idx];
    float mx = 0.0f;
    for (int idx = t; idx < BB * NN; idx += 256) mx = fmaxf(mx, g_norm[idx]);
    s_red[t] = mx;
    __syncthreads();
    for (int s = 128; s > 0; s >>= 1) {
        if (t < s) s_red[t] = fmaxf(s_red[t], s_red[t + s]);
        __syncthreads();
    }
    float maxnorm = s_red[0];

    for (int idx = t; idx < NN * FF; idx += 256) {
        int j = idx >> 6, k = idx & 63;
        float c = 0.0f;
        if (k < 63) {
            const float* w = s_wee + k * 8;
            const float* nf = s_nf + j * 8;
#pragma unroll
            for (int d = 0; d < 7; d++) c = fmaf(w[d + 1], nf[d], c);
        }
        s_c[idx] = c;
    }
    for (int idx = t; idx < 16 * FF; idx += 256) {
        int r = idx >> 6, f = idx & 63;
        const float* w = s_wi + f * 8;
        const float* nf = s_nf + (r0 + r) * 8;
        float e = 0.0f;
#pragma unroll
        for (int d = 0; d < 7; d++) e = fmaf(w[d], nf[d], e);
        g_curA[(b * NN + r0 + r) * FF + f] = fmaxf(e, 0.0f);
    }
    __syncthreads();

    {
        int r = t >> 4, g = t & 15;
        int f0 = g << 2;
        float4 w0;
        w0.x = s_wee[(f0 + 0) * 8];
        w0.y = s_wee[(f0 + 1) * 8];
        w0.z = s_wee[(f0 + 2) * 8];
        w0.w = s_wee[(f0 + 3) * 8];
        float4 acc = make_float4(0.f, 0.f, 0.f, 0.f);
        const float* arow = s_adj + r * 129;
        for (int j = 0; j < NN; j++) {
            float a = arow[j];
            if (a != 0.0f) {
                float4 c = *(const float4*)(s_c + j * 64 + f0);
                acc.x += fmaxf(fmaf(a, w0.x, c.x), 0.0f);
                acc.y += fmaxf(fmaf(a, w0.y, c.y), 0.0f);
                acc.z += fmaxf(fmaf(a, w0.z, c.z), 0.0f);
                acc.w += fmaxf(fmaf(a, w0.w, c.w), 0.0f);
            }
        }
        float nrm = s_nm[r0 + r];
        float inv = 1.0f / nrm;
        float* es = s_es + r * 64 + f0;
        es[0] = acc.x * inv;
        es[1] = acc.y * inv;
        es[2] = acc.z * inv;
        es[3] = (g == 15) ? (nrm / maxnorm) : acc.w * inv;
    }
    __syncthreads();

    for (int idx = t; idx < 16 * FF; idx += 256) {
        int r = idx >> 6, f = idx & 63;
        const float* e = s_es + r * 64;
        float acc = 0.0f;
#pragma unroll 16
        for (int k = 0; k < 64; k++) acc = fmaf(s_weft[k * 65 + f], e[k], acc);
        g_ee[(b * NN + r0 + r) * FF + f] = fmaxf(acc, 0.0f);
    }
}

// ---------------- K3: MPNN layer (FFMA2, K-split-2, skewed halves) ---------
// Pair buffers (cur, w): two 64-row halves of 64 words, half1 skewed +16 words.
// Dup buffers (aT, xT): two 64-row halves of 32 words, half1 skewed +4 words.
#define HPW 4112              // pair half-1 word offset (64*64 + 16)
#define PAIR_WORDS 8208       // 4112 + 4096
#define HDW 2052              // dup half-1 word offset (64*32 + 4)
#define DUP_WORDS 4100        // 2052 + 2048
#define L_TOT_WORDS (2*PAIR_WORDS + 2*DUP_WORDS + 16)
#define L_SMEM_BYTES (L_TOT_WORDS * 4)

// res[ri][fj] = sum_k dup[k][r]*pair[k][f], K-split over lane bit 0 (kk).
__device__ __forceinline__ void mma_stage(unsigned da, unsigned pa, float res[4][4]) {
    unsigned long long acc00 = 0, acc01 = 0, acc10 = 0, acc11 = 0;
    unsigned long long acc20 = 0, acc21 = 0, acc30 = 0, acc31 = 0;
#pragma unroll 16
    for (int it = 0; it < 64; it++) {
        unsigned long long a0, a1, a2, a3, c0, c1;
        asm volatile("ld.shared.v2.b64 {%0,%1}, [%2];" : "=l"(a0), "=l"(a1) : "r"(da));
        asm volatile("ld.shared.v2.b64 {%0,%1}, [%2];" : "=l"(a2), "=l"(a3) : "r"(da + 16));
        asm volatile("ld.shared.v2.b64 {%0,%1}, [%2];" : "=l"(c0), "=l"(c1) : "r"(pa));
        asm("fma.rn.f32x2 %0, %1, %2, %0;" : "+l"(acc00) : "l"(a0), "l"(c0));
        asm("fma.rn.f32x2 %0, %1, %2, %0;" : "+l"(acc01) : "l"(a0), "l"(c1));
        asm("fma.rn.f32x2 %0, %1, %2, %0;" : "+l"(acc10) : "l"(a1), "l"(c0));
        asm("fma.rn.f32x2 %0, %1, %2, %0;" : "+l"(acc11) : "l"(a1), "l"(c1));
        asm("fma.rn.f32x2 %0, %1, %2, %0;" : "+l"(acc20) : "l"(a2), "l"(c0));
        asm("fma.rn.f32x2 %0, %1, %2, %0;" : "+l"(acc21) : "l"(a2), "l"(c1));
        asm("fma.rn.f32x2 %0, %1, %2, %0;" : "+l"(acc30) : "l"(a3), "l"(c0));
        asm("fma.rn.f32x2 %0, %1, %2, %0;" : "+l"(acc31) : "l"(a3), "l"(c1));
        da += 128;            // 32 words per k
        pa += 256;            // 64 words per k
    }
    unsigned long long av[4][2] = {{acc00, acc01}, {acc10, acc11},
                                   {acc20, acc21}, {acc30, acc31}};
#pragma unroll
    for (int ri = 0; ri < 4; ri++)
#pragma unroll
        for (int p = 0; p < 2; p++) {
            unsigned long long v = av[ri][p];
            unsigned long long o = __shfl_xor_sync(0xffffffffu, v, 1);
            float lo, hi, lo2, hi2;
            asm("mov.b64 {%0,%1}, %2;" : "=f"(lo), "=f"(hi) : "l"(v));
            asm("mov.b64 {%0,%1}, %2;" : "=f"(lo2), "=f"(hi2) : "l"(o));
            res[ri][2 * p] = lo + lo2;
            res[ri][2 * p + 1] = hi + hi2;
        }
}

// grid = 32 b * 8 chunks (16 rows), 128 threads, 2 blocks/SM
__global__ __launch_bounds__(128, 2)
void k_layer(const float* __restrict__ obs, int layer, int flip) {
    extern __shared__ float sm[];
    float* s_cur = sm;                          // pair: full-batch cur
    float* s_w   = sm + PAIR_WORDS;             // pair: weights [k][f]
    float* s_aT  = s_w + PAIR_WORDS;            // dup:  adj^T [j][2r]
    float* s_xT  = s_aT + DUP_WORDS;            // dup:  concat-input^T [k][2r]
    float* s_nm  = s_xT + DUP_WORDS;            // [16]

    const float* g_in = flip ? g_curB : g_curA;
    float* g_out      = flip ? g_curA : g_curB;
    const float* Wm = g_Wt + (layer * 2) * 8192;
    const float* Wu = g_Wt + (layer * 2 + 1) * 8192;

    int t = threadIdx.x;
    int b = blockIdx.x >> 3;
    int r0 = (blockIdx.x & 7) << 4;
    const float* ob = obs + b * NN * DD;

    // ---- fills ----
    {
        const float4* gc = (const float4*)(g_in + b * 8192);
        for (int i = t; i < 2048; i += 128) {
            float4 v = gc[i];
            int j = i >> 4, fq = i & 15;
            *(float4*)&s_cur[(j >> 6) * HPW + (j & 63) * 64 + fq * 4] = v;
        }
        const float4* gw = (const float4*)Wm;
        for (int i = t; i < 2048; i += 128) {
            float4 v = gw[i];
            int k = i >> 4, fq = i & 15;
            *(float4*)&s_w[(k >> 6) * HPW + (k & 63) * 64 + fq * 4] = v;
        }
        for (int i = t; i < 2048; i += 128) {
            int r = i >> 7, j = i & 127;
            float a = ob[(r0 + r) * DD + ADJ_OFF + j];
            float2 d = make_float2(a, a);
            *(float2*)&s_aT[(j >> 6) * HDW + (j & 63) * 32 + 2 * r] = d;
        }
        for (int i = t; i < 1024; i += 128) {
            int r = i >> 6, f = i & 63;
            float e = g_ee[(b * NN + r0 + r) * FF + f];
            float2 d = make_float2(e, e);
            *(float2*)&s_xT[HDW + f * 32 + 2 * r] = d;
        }
        if (t < 16) s_nm[t] = g_norm[b * NN + r0 + t];
    }
    __syncthreads();

    int kk = t & 1, rg = (t >> 1) & 3, fg = t >> 3;
    unsigned sb = (unsigned)__cvta_generic_to_shared(sm);
    unsigned CU = sb;
    unsigned WB = sb + PAIR_WORDS * 4;
    unsigned AT = WB + PAIR_WORDS * 4;
    unsigned XT = AT + DUP_WORDS * 4;
    unsigned da0 = (unsigned)(kk * HDW * 4 + rg * 32);
    unsigned pa0 = (unsigned)(kk * HPW * 4 + fg * 16);

    float res[4][4];

    // ---- stage 1: agg = adj @ cur / norm -> xT half 0 ----
    mma_stage(AT + da0, CU + pa0, res);
    if (kk == 0) {
#pragma unroll
        for (int ri = 0; ri < 4; ri++) {
            int r = rg * 4 + ri;
            float inv = 1.0f / s_nm[r];
#pragma unroll
            for (int fj = 0; fj < 4; fj++) {
                float v = res[ri][fj] * inv;
                int f = fg * 4 + fj;
                *(float2*)&s_xT[f * 32 + 2 * r] = make_float2(v, v);
            }
        }
    }
    __syncthreads();

    // ---- stage 2: msg = relu([agg, ee] @ Wm^T) ----
    mma_stage(XT + da0, WB + pa0, res);
    __syncthreads();
    if (kk == 0) {
#pragma unroll
        for (int ri = 0; ri < 4; ri++) {
            int r = rg * 4 + ri;
#pragma unroll
            for (int fj = 0; fj < 4; fj++) {
                float v = fmaxf(res[ri][fj], 0.0f);
                int f = fg * 4 + fj;
                *(float2*)&s_xT[HDW + f * 32 + 2 * r] = make_float2(v, v);
            }
        }
    }
    // own cur rows -> xT half 0; reload weights (Wu)
    for (int i = t; i < 1024; i += 128) {
        int r = i >> 6, f = i & 63;
        int jr = r0 + r;
        float c = s_cur[(jr >> 6) * HPW + (jr & 63) * 64 + f];
        *(float2*)&s_xT[f * 32 + 2 * r] = make_float2(c, c);
    }
    {
        const float4* gw2 = (const float4*)Wu;
        for (int i = t; i < 2048; i += 128) {
            float4 v = gw2[i];
            int k = i >> 4, fq = i & 15;
            *(float4*)&s_w[(k >> 6) * HPW + (k & 63) * 64 + fq * 4] = v;
        }
    }
    __syncthreads();

    // ---- stage 3: cur' = relu([cur, msg] @ Wu^T) -> global ----
    mma_stage(XT + da0, WB + pa0, res);
    if (kk == 0) {
#pragma unroll
        for (int ri = 0; ri < 4; ri++) {
            int rg_out = (b * NN + r0 + rg * 4 + ri) * FF + fg * 4;
            float4 o;
            o.x = fmaxf(res[ri][0], 0.0f);
            o.y = fmaxf(res[ri][1], 0.0f);
            o.z = fmaxf(res[ri][2], 0.0f);
            o.w = fmaxf(res[ri][3], 0.0f);
            *(float4*)&g_out[rg_out] = o;
        }
    }
}

// ---------------- K4: pooling + readout precompute -------------------------
__global__ void k_pool(const float* __restrict__ Wp,
                       const float* __restrict__ Wr,
                       const float* __restrict__ br) {
    __shared__ float s_cur[8192];
    __shared__ float s_pool[64];
    __shared__ float s_rhp[64];
    int b = blockIdx.x, t = threadIdx.x;
    for (int idx = t; idx < 8192; idx += 256) s_cur[idx] = g_curB[b * 8192 + idx];
    __syncthreads();
    if (t < 64) {
        float s = 0.0f;
#pragma unroll 8
        for (int i = 0; i < NN; i++) s += s_cur[i * 64 + t];
        s_pool[t] = s * (1.0f / (float)NN);
    }
    __syncthreads();
    if (t < 64) {
        float acc = 0.0f;
#pragma unroll 8
        for (int g = 0; g < 64; g++) acc = fmaf(Wp[t * 64 + g], s_pool[g], acc);
        s_rhp[t] = fmaxf(acc, 0.0f);
    }
    __syncthreads();
    if (t < 4) {
        float acc = br[t];
#pragma unroll 8
        for (int f = 0; f < 64; f++) acc = fmaf(Wr[t * 192 + f], s_rhp[f], acc);
        g_Abias[b * 4 + t] = acc;
    }
    for (int o = t; o < 1024; o += 256) {
        int i = o >> 3, c = o & 7;
        int oo = c & 3;
        const float* w = Wr + oo * 192 + ((c >= 4) ? 128 : 64);
        const float* cu = s_cur + i * 64;
        float acc = 0.0f;
#pragma unroll 8
        for (int f = 0; f < 64; f++) acc = fmaf(w[f], cu[f], acc);
        g_PQ[(b * NN + i) * 8 + c] = acc;
    }
}

// ---------------- K5: broadcast readout write ------------------------------
__global__ void k_out(float4* __restrict__ out) {
    int idx = blockIdx.x * blockDim.x + threadIdx.x;
    int j = idx & 127;
    int bi = idx >> 7;
    int b = idx >> 14;
    float4 A = *(const float4*)(g_Abias + b * 4);
    float4 P = *(const float4*)(g_PQ + bi * 8);
    float4 Q = *(const float4*)(g_PQ + (((b << 7) | j) * 8 + 4));
    float4 r;
    r.x = A.x + P.x + Q.x;
    r.y = A.y + P.y + Q.y;
    r.z = A.z + P.z + Q.z;
    r.w = A.w + P.w + Q.w;
    out[idx] = r;
}

// ---------------- host launcher --------------------------------------------
extern "C" void kernel_launch(void* const* d_in, const int* in_sizes, int n_in,
                              void* d_out, int out_size) {
    const float* obs    = (const float*)d_in[0];
    const float* W_init = (const float*)d_in[1];
    const float* W_ee   = (const float*)d_in[2];
    const float* W_ef   = (const float*)d_in[3];
    const float* W_msg  = (const float*)d_in[4];
    const float* W_upd  = (const float*)d_in[5];
    const float* W_pool = (const float*)d_in[6];
    const float* W_read = (const float*)d_in[7];
    const float* b_read = (const float*)d_in[8];

    cudaFuncSetAttribute(k_edge, cudaFuncAttributeMaxDynamicSharedMemorySize,
                         EDGE_SMEM_FLOATS * 4);
    cudaFuncSetAttribute(k_layer, cudaFuncAttributeMaxDynamicSharedMemorySize,
                         L_SMEM_BYTES);

    k_wt<<<6, 256>>>(W_msg, W_upd);
    k_norm<<<BB, 128>>>(obs);
    k_edge<<<BB * 8, 256, EDGE_SMEM_FLOATS * 4>>>(obs, W_init, W_ee, W_ef);
    for (int l = 0; l < 3; l++) {
        k_layer<<<BB * 8, 128, L_SMEM_BYTES>>>(obs, l, l & 1);
    }
    k_pool<<<BB, 256>>>(W_pool, W_read, b_read);
    k_out<<<(BB * NN * NN) / 256, 256>>>((float4*)d_out);
}

// round 5
// speedup vs baseline: 1.1362x; 1.1362x over previous
#include <cuda_runtime.h>

#define BB 32
#define NN 128
#define DD 135
#define OBS 7
#define FF 64
#define ADJ_OFF 7
#define GRID 128
#define NT 512

// ---------------- device global scratch (allocation-free) ----------------
__device__ float g_norm[BB * NN];
__device__ float g_cur[BB * NN * FF];
__device__ float g_X[BB * NN * 128];      // [agg | ee] per (b,node)
__device__ float g_Wt[6 * 128 * 64];      // transposed W_msg/W_upd
__device__ float g_PQ[BB * NN * 8];
__device__ float g_Abias[BB * 4];
__device__ unsigned g_cnt = 0;
__device__ unsigned g_gen = 0;

// ---------------- grid-wide barrier (all GRID blocks resident) -------------
__device__ __forceinline__ void gbar() {
    __threadfence();
    __syncthreads();
    if (threadIdx.x == 0) {
        unsigned gen = atomicAdd(&g_gen, 0u);
        unsigned a = atomicAdd(&g_cnt, 1u);
        if (a == GRID - 1) {
            atomicExch(&g_cnt, 0u);
            __threadfence();
            atomicAdd(&g_gen, 1u);
        } else {
            while (atomicAdd(&g_gen, 0u) == gen) __nanosleep(64);
        }
    }
    __syncthreads();
}

// smem layout constants (floats)
#define PADW 68                    // row pitch for [128][64] matrices (16B aligned)
#define SMEM_FLOATS 25600          // max over phases (S2/S3: 2*8704+4096+2048+2048)

__global__ __launch_bounds__(NT, 1)
void k_mpnn(const float* __restrict__ obs,
            const float* __restrict__ W_init,
            const float* __restrict__ W_ee,
            const float* __restrict__ W_ef,
            const float* __restrict__ Wm_g,
            const float* __restrict__ Wu_g,
            const float* __restrict__ Wp,
            const float* __restrict__ Wr,
            const float* __restrict__ br,
            float4* __restrict__ out) {
    extern __shared__ float sm[];
    const int t = threadIdx.x;
    const int bid = blockIdx.x;

    // ================= P0: weight transpose + norms ========================
    if (bid < 6) {
        const float* src = (bid & 1) ? (Wu_g + (bid >> 1) * 8192)
                                     : (Wm_g + (bid >> 1) * 8192);
        float* dst = g_Wt + bid * 8192;
        for (int i = t; i < 8192; i += NT) {
            int f = i >> 7, k = i & 127;
            dst[k * 64 + f] = src[i];
        }
    } else if (bid < 38) {
        int b = bid - 6;
        float* part = sm;                       // [4][128]
        int q = t >> 7, col = t & 127;
        const float* o = obs + b * (NN * DD) + ADJ_OFF;
        float c = 0.f;
        for (int i = q * 32; i < q * 32 + 32; i++)
            c += (o[i * DD + col] != 0.0f) ? 1.0f : 0.0f;
        part[q * 128 + col] = c;
        __syncthreads();
        if (t < 128) {
            float s = part[t] + part[128 + t] + part[256 + t] + part[384 + t];
            g_norm[b * NN + t] = (s == 0.0f) ? 1.0f : s;
        }
    }
    gbar();

    // ================= P1: edge stage + init embedding =====================
    {
        int b = bid >> 2;
        int r0 = (bid & 3) << 5;
        const float* ob = obs + b * NN * DD;
        float* s_nf   = sm;             // 1024
        float* s_wee  = sm + 1024;      // 512
        float* s_wi   = sm + 1536;      // 512
        float* s_weft = sm + 2048;      // 64*65 = 4160
        float* s_c    = sm + 6208;      // 128*64 = 8192
        float* s_adj  = sm + 14400;     // 32*128 = 4096
        float* s_es   = sm + 18496;     // 32*64 = 2048
        float* s_nm   = sm + 20544;     // 32
        float* s_red  = sm + 20608;     // 512

        for (int i = t; i < 1024; i += NT) {
            int j = i >> 3, d = i & 7;
            s_nf[i] = (d < 7) ? ob[j * DD + d] : 0.f;
        }
        for (int i = t; i < 512; i += NT)
            s_wee[i] = (i < 504) ? W_ee[i] : 0.f;          // 63*8 valid
        for (int i = t; i < 512; i += NT) {
            int f = i >> 3, d = i & 7;
            s_wi[i] = (d < 7) ? W_init[f * 7 + d] : 0.f;
        }
        for (int i = t; i < 4096; i += NT) {
            int f = i >> 6, k = i & 63;
            s_weft[k * 65 + f] = W_ef[i];
        }
        for (int i = t; i < 4096; i += NT) {
            int r = i >> 7, j = i & 127;
            s_adj[i] = ob[(r0 + r) * DD + ADJ_OFF + j];
        }
        if (t < 32) s_nm[t] = __ldcg(&g_norm[b * NN + r0 + t]);
        float mx = 0.f;
        for (int i = t; i < BB * NN; i += NT) mx = fmaxf(mx, __ldcg(&g_norm[i]));
        s_red[t] = mx;
        __syncthreads();
        for (int s = 256; s > 0; s >>= 1) {
            if (t < s) s_red[t] = fmaxf(s_red[t], s_red[t + s]);
            __syncthreads();
        }
        float inv_maxnorm = 1.0f / s_red[0];

        // per-node edge constant c[j][k] = W_ee[k,1:8] . nf[j]
        for (int i = t; i < 8192; i += NT) {
            int j = i >> 6, k = i & 63;
            float c = 0.f;
            if (k < 63) {
                const float* w = s_wee + k * 8;
                const float* nf = s_nf + j * 8;
#pragma unroll
                for (int d = 0; d < 7; d++) c = fmaf(w[d + 1], nf[d], c);
            }
            s_c[i] = c;
        }
        // init embedding for our 32 rows
        for (int i = t; i < 2048; i += NT) {
            int r = i >> 6, f = i & 63;
            const float* w = s_wi + f * 8;
            const float* nf = s_nf + (r0 + r) * 8;
            float e = 0.f;
#pragma unroll
            for (int d = 0; d < 7; d++) e = fmaf(w[d], nf[d], e);
            __stcg(&g_cur[(b * NN + r0 + r) * FF + f], fmaxf(e, 0.f));
        }
        __syncthreads();

        // edge sum: thread (r, fg) -> 4 features
        {
            int r = t >> 4, fg = t & 15, f0 = fg << 2;
            float w0x = s_wee[(f0 + 0) * 8], w0y = s_wee[(f0 + 1) * 8];
            float w0z = s_wee[(f0 + 2) * 8], w0w = s_wee[(f0 + 3) * 8];
            float ax = 0.f, ay = 0.f, az = 0.f, aw = 0.f;
            const float* arow = s_adj + r * 128;
            for (int j = 0; j < NN; j++) {
                float a = arow[j];
                if (a != 0.f) {
                    float4 c = *(const float4*)(s_c + j * 64 + f0);
                    ax += fmaxf(fmaf(a, w0x, c.x), 0.f);
                    ay += fmaxf(fmaf(a, w0y, c.y), 0.f);
                    az += fmaxf(fmaf(a, w0z, c.z), 0.f);
                    aw += fmaxf(fmaf(a, w0w, c.w), 0.f);
                }
            }
            float nrm = s_nm[r];
            float inv = 1.0f / nrm;
            float* es = s_es + r * 64 + f0;
            es[0] = ax * inv;
            es[1] = ay * inv;
            es[2] = az * inv;
            es[3] = (fg == 15) ? (nrm * inv_maxnorm) : aw * inv;
        }
        __syncthreads();

        // edge_emb = relu(es @ W_ef^T) -> g_X[..][64:128]
        for (int i = t; i < 2048; i += NT) {
            int r = i >> 6, f = i & 63;
            const float* e = s_es + r * 64;
            float acc = 0.f;
#pragma unroll 8
            for (int k = 0; k < 64; k++) acc = fmaf(s_weft[k * 65 + f], e[k], acc);
            __stcg(&g_X[(b * NN + r0 + r) * 128 + 64 + f], fmaxf(acc, 0.f));
        }
    }
    gbar();

    // ================= layers ==============================================
    for (int l = 0; l < 3; l++) {
        // ---- S1: agg = adj @ cur / norm -> g_X[..][0:64] ----
        {
            int b = bid >> 2, r0 = (bid & 3) << 5;
            float* s_cur = sm;                     // [128][PADW]
            float* s_A   = sm + 128 * PADW;        // [32][128]
            float* s_nm  = s_A + 4096;             // 32
            const float4* gc = (const float4*)(g_cur + b * 8192);
            for (int i = t; i < 2048; i += NT) {
                float4 v = __ldcg(&gc[i]);
                int j = i >> 4, q = i & 15;
                *(float4*)&s_cur[j * PADW + q * 4] = v;
            }
            const float* ob = obs + b * NN * DD;
            for (int i = t; i < 4096; i += NT) {
                int r = i >> 7, j = i & 127;
                s_A[i] = ob[(r0 + r) * DD + ADJ_OFF + j];
            }
            if (t < 32) s_nm[t] = __ldcg(&g_norm[b * NN + r0 + t]);
            __syncthreads();

            int r = t >> 4, cg = t & 15;
            const float* arow = s_A + r * 128;
            float ax = 0.f, ay = 0.f, az = 0.f, aw = 0.f;
#pragma unroll 8
            for (int k = 0; k < 128; k++) {
                float a = arow[k];
                float4 c = *(const float4*)(s_cur + k * PADW + cg * 4);
                ax = fmaf(a, c.x, ax);
                ay = fmaf(a, c.y, ay);
                az = fmaf(a, c.z, az);
                aw = fmaf(a, c.w, aw);
            }
            float inv = 1.0f / s_nm[r];
            float4 o = make_float4(ax * inv, ay * inv, az * inv, aw * inv);
            __stcg((float4*)&g_X[(b * NN + r0 + r) * 128 + cg * 4], o);
        }
        gbar();

        // ---- S2+S3: msg = relu(X@Wm^T); cur' = relu([cur|msg]@Wu^T) ----
        {
            int b = bid >> 2, r0 = (bid & 3) << 5;
            float* s_w0 = sm;                      // [128][PADW]
            float* s_w1 = sm + 128 * PADW;         // [128][PADW]
            float* s_X  = s_w1 + 128 * PADW;       // [32][128]
            float* s_ms = s_X + 4096;              // [32][64]
            float* s_cr = s_ms + 2048;             // [32][64]
            const float4* w0g = (const float4*)(g_Wt + (l * 2) * 8192);
            const float4* w1g = (const float4*)(g_Wt + (l * 2 + 1) * 8192);
            for (int i = t; i < 2048; i += NT) {
                int k = i >> 4, q = i & 15;
                *(float4*)&s_w0[k * PADW + q * 4] = w0g[i];
                *(float4*)&s_w1[k * PADW + q * 4] = w1g[i];
            }
            const float4* xg = (const float4*)(g_X + (b * NN + r0) * 128);
            for (int i = t; i < 1024; i += NT)
                *(float4*)&s_X[i * 4] = __ldcg(&xg[i]);
            const float4* crg = (const float4*)(g_cur + (b * NN + r0) * 64);
            for (int i = t; i < 512; i += NT)
                *(float4*)&s_cr[i * 4] = __ldcg(&crg[i]);
            __syncthreads();

            int r = t >> 4, cg = t & 15;
            // msg
            {
                const float* xr = s_X + r * 128;
                float ax = 0.f, ay = 0.f, az = 0.f, aw = 0.f;
#pragma unroll 8
                for (int k = 0; k < 128; k++) {
                    float x = xr[k];
                    float4 w = *(const float4*)(s_w0 + k * PADW + cg * 4);
                    ax = fmaf(x, w.x, ax);
                    ay = fmaf(x, w.y, ay);
                    az = fmaf(x, w.z, az);
                    aw = fmaf(x, w.w, aw);
                }
                float4 m = make_float4(fmaxf(ax, 0.f), fmaxf(ay, 0.f),
                                       fmaxf(az, 0.f), fmaxf(aw, 0.f));
                *(float4*)&s_ms[r * 64 + cg * 4] = m;
            }
            __syncthreads();
            // upd
            {
                const float* cr = s_cr + r * 64;
                const float* ms = s_ms + r * 64;
                float ax = 0.f, ay = 0.f, az = 0.f, aw = 0.f;
#pragma unroll 8
                for (int k = 0; k < 64; k++) {
                    float x = cr[k];
                    float4 w = *(const float4*)(s_w1 + k * PADW + cg * 4);
                    ax = fmaf(x, w.x, ax);
                    ay = fmaf(x, w.y, ay);
                    az = fmaf(x, w.z, az);
                    aw = fmaf(x, w.w, aw);
                }
#pragma unroll 8
                for (int k = 0; k < 64; k++) {
                    float x = ms[k];
                    float4 w = *(const float4*)(s_w1 + (64 + k) * PADW + cg * 4);
                    ax = fmaf(x, w.x, ax);
                    ay = fmaf(x, w.y, ay);
                    az = fmaf(x, w.z, az);
                    aw = fmaf(x, w.w, aw);
                }
                float4 o = make_float4(fmaxf(ax, 0.f), fmaxf(ay, 0.f),
                                       fmaxf(az, 0.f), fmaxf(aw, 0.f));
                __stcg((float4*)&g_cur[(b * NN + r0 + r) * 64 + cg * 4], o);
            }
        }
        gbar();
    }

    // ================= P4: pooling + readout precompute ====================
    if (bid < 32) {
        int b = bid;
        float* s_cur  = sm;            // 8192
        float* s_part = sm + 8192;     // 512
        float* s_pool = sm + 8704;     // 64
        float* s_rhp  = sm + 8768;     // 64
        const float4* gc = (const float4*)(g_cur + b * 8192);
        for (int i = t; i < 2048; i += NT)
            *(float4*)&s_cur[i * 4] = __ldcg(&gc[i]);
        __syncthreads();
        {
            int f = t & 63, g = t >> 6;
            float s = 0.f;
            for (int i = g * 16; i < g * 16 + 16; i++) s += s_cur[i * 64 + f];
            s_part[g * 64 + f] = s;
        }
        __syncthreads();
        if (t < 64) {
            float s = 0.f;
#pragma unroll
            for (int g = 0; g < 8; g++) s += s_part[g * 64 + t];
            s_pool[t] = s * (1.0f / 128.0f);
        }
        __syncthreads();
        if (t < 64) {
            float acc = 0.f;
            for (int g = 0; g < 64; g++) acc = fmaf(Wp[t * 64 + g], s_pool[g], acc);
            s_rhp[t] = fmaxf(acc, 0.f);
        }
        __syncthreads();
        if (t < 4) {
            float acc = br[t];
            for (int f = 0; f < 64; f++) acc = fmaf(Wr[t * 192 + f], s_rhp[f], acc);
            g_Abias[b * 4 + t] = acc;
        }
        for (int o = t; o < 1024; o += NT) {
            int i = o >> 3, c = o & 7, oo = c & 3;
            const float* w = Wr + oo * 192 + ((c >= 4) ? 128 : 64);
            const float* cu = s_cur + i * 64;
            float acc = 0.f;
#pragma unroll 8
            for (int f = 0; f < 64; f++) acc = fmaf(w[f], cu[f], acc);
            g_PQ[(b * NN + i) * 8 + c] = acc;
        }
    }
    gbar();

    // ================= P5: broadcast readout write =========================
    {
        int b = bid >> 2, i0 = (bid & 3) << 5;
        float4* s_Q = (float4*)sm;                 // 128
        float4* s_P = (float4*)(sm + 512);         // 32
        if (t < 128) s_Q[t] = __ldcg((const float4*)&g_PQ[(b * NN + t) * 8 + 4]);
        else if (t < 160) s_P[t - 128] = __ldcg((const float4*)&g_PQ[(b * NN + i0 + (t - 128)) * 8]);
        __syncthreads();
        float4 A = __ldcg((const float4*)&g_Abias[b * 4]);
        int i = i0 + (t >> 4), j0 = (t & 15) << 3;
        float4 P = s_P[t >> 4];
        float px = A.x + P.x, py = A.y + P.y, pz = A.z + P.z, pw = A.w + P.w;
        float4* op = out + ((b * NN + i) * NN + j0);
#pragma unroll
        for (int j = 0; j < 8; j++) {
            float4 Q = s_Q[j0 + j];
            float4 rr = make_float4(px + Q.x, py + Q.y, pz + Q.z, pw + Q.w);
            op[j] = rr;
        }
    }
}

// ---------------- host launcher --------------------------------------------
extern "C" void kernel_launch(void* const* d_in, const int* in_sizes, int n_in,
                              void* d_out, int out_size) {
    const float* obs    = (const float*)d_in[0];
    const float* W_init = (const float*)d_in[1];
    const float* W_ee   = (const float*)d_in[2];
    const float* W_ef   = (const float*)d_in[3];
    const float* W_msg  = (const float*)d_in[4];
    const float* W_upd  = (const float*)d_in[5];
    const float* W_pool = (const float*)d_in[6];
    const float* W_read = (const float*)d_in[7];
    const float* b_read = (const float*)d_in[8];

    cudaFuncSetAttribute(k_mpnn, cudaFuncAttributeMaxDynamicSharedMemorySize,
                         SMEM_FLOATS * 4);
    k_mpnn<<<GRID, NT, SMEM_FLOATS * 4>>>(obs, W_init, W_ee, W_ef,
                                          W_msg, W_upd, W_pool, W_read, b_read,
                                          (float4*)d_out);
}

// round 8
// speedup vs baseline: 1.2574x; 1.1066x over previous
#include <cuda_runtime.h>

#define BB 32
#define NN 128
#define DD 135
#define ADJ_OFF 7
#define GRID 128
#define NT 512

#define PX 36              // pitch of transposed [k][32-row] buffers
#define PW 68              // pitch of [k][64-col] buffers
#define OFF_AT 0           // adjT      [128][PX]  (persistent)
#define OFF_XT 4608        // x input   [128][PX]  (agg rows 0-63, ee rows 64-127)
#define OFF_CT 9216        // upd input [128][PX]  (curT rows 0-63, msgT rows 64-127)
#define OFF_W  13824       // [128][PW] weights / full-batch cur / edge-c
#define OFF_NM 22528       // 32 norms
#define SMW    22592

__device__ float g_norm[BB * NN];
__device__ float g_cur[BB * NN * 64];
__device__ float g_Wt[6 * 128 * 64];   // transposed W_msg/W_upd [m][k][f]
__device__ float g_PQ[BB * NN * 8];
__device__ float g_Abias[BB * 4];
__device__ unsigned g_cnt = 0, g_gen = 0;

__device__ __forceinline__ void gbar() {
    __threadfence();
    __syncthreads();
    if (threadIdx.x == 0) {
        unsigned gen = atomicAdd(&g_gen, 0u);
        unsigned a = atomicAdd(&g_cnt, 1u);
        if (a == GRID - 1) {
            atomicExch(&g_cnt, 0u);
            __threadfence();
            atomicAdd(&g_gen, 1u);
        } else {
            while (atomicAdd(&g_gen, 0u) == gen) __nanosleep(64);
        }
    }
    __syncthreads();
}

__device__ __forceinline__ float rsum4(float v) {
    v += __shfl_xor_sync(0xffffffffu, v, 1);
    v += __shfl_xor_sync(0xffffffffu, v, 2);
    return v;
}

// res[q][e] = sum_k xT[k][rg*4+q] * w[k][fg*4+e]
// xp = &xT[kk*PX + rg*4], wp = &w[kk*PW + fg*4]; k-split 4 over lane bits 0-1.
template <int NK>
__device__ __forceinline__ void gemm32(const float* xp, const float* wp,
                                       float res[4][4]) {
    float4 a0 = {0.f, 0.f, 0.f, 0.f}, a1 = a0, a2 = a0, a3 = a0;
#pragma unroll 8
    for (int i = 0; i < NK; i++) {
        float4 x = *(const float4*)xp;
        float4 w = *(const float4*)wp;
        a0.x = fmaf(x.x, w.x, a0.x); a0.y = fmaf(x.x, w.y, a0.y);
        a0.z = fmaf(x.x, w.z, a0.z); a0.w = fmaf(x.x, w.w, a0.w);
        a1.x = fmaf(x.y, w.x, a1.x); a1.y = fmaf(x.y, w.y, a1.y);
        a1.z = fmaf(x.y, w.z, a1.z); a1.w = fmaf(x.y, w.w, a1.w);
        a2.x = fmaf(x.z, w.x, a2.x); a2.y = fmaf(x.z, w.y, a2.y);
        a2.z = fmaf(x.z, w.z, a2.z); a2.w = fmaf(x.z, w.w, a2.w);
        a3.x = fmaf(x.w, w.x, a3.x); a3.y = fmaf(x.w, w.y, a3.y);
        a3.z = fmaf(x.w, w.z, a3.z); a3.w = fmaf(x.w, w.w, a3.w);
        xp += 4 * PX;
        wp += 4 * PW;
    }
    res[0][0] = rsum4(a0.x); res[0][1] = rsum4(a0.y);
    res[0][2] = rsum4(a0.z); res[0][3] = rsum4(a0.w);
    res[1][0] = rsum4(a1.x); res[1][1] = rsum4(a1.y);
    res[1][2] = rsum4(a1.z); res[1][3] = rsum4(a1.w);
    res[2][0] = rsum4(a2.x); res[2][1] = rsum4(a2.y);
    res[2][2] = rsum4(a2.z); res[2][3] = rsum4(a2.w);
    res[3][0] = rsum4(a3.x); res[3][1] = rsum4(a3.y);
    res[3][2] = rsum4(a3.z); res[3][3] = rsum4(a3.w);
}

__global__ __launch_bounds__(NT)
void k_mpnn(const float* __restrict__ obs,
            const float* __restrict__ W_init,
            const float* __restrict__ W_ee,
            const float* __restrict__ W_ef,
            const float* __restrict__ Wm_g,
            const float* __restrict__ Wu_g,
            const float* __restrict__ Wp,
            const float* __restrict__ Wr,
            const float* __restrict__ br,
            float4* __restrict__ out) {
    extern __shared__ float sm[];
    const int t = threadIdx.x;
    const int bid = blockIdx.x;
    float* s_aT = sm + OFF_AT;
    float* s_xT = sm + OFF_XT;
    float* s_cT = sm + OFF_CT;
    float* s_w  = sm + OFF_W;
    float* s_nm = sm + OFF_NM;

    const int b  = bid >> 2;
    const int r0 = (bid & 3) << 5;
    const float* ob = obs + b * NN * DD;

    // lane decomposition for GEMM32 stages
    const int lane = t & 31, warp = t >> 5;
    const int kk = lane & 3;
    const int fg = ((warp & 1) << 3) | (lane >> 2);   // 0..15
    const int rg = warp >> 1;                          // 0..7

    // ================= P0: weight transpose + norms ========================
    if (bid < 6) {
        const float* src = (bid & 1) ? (Wu_g + (bid >> 1) * 8192)
                                     : (Wm_g + (bid >> 1) * 8192);
        float* dst = g_Wt + bid * 8192;
        for (int i = t; i < 8192; i += NT) {
            int f = i >> 7, k = i & 127;
            __stcg(&dst[k * 64 + f], src[i]);
        }
    } else if (bid < 38) {
        int bb2 = bid - 6;
        float* part = sm;                       // [4][128]
        int q = t >> 7, col = t & 127;
        const float* o = obs + bb2 * (NN * DD) + ADJ_OFF;
        float c = 0.f;
        for (int i = q * 32; i < q * 32 + 32; i++)
            c += (o[i * DD + col] != 0.0f) ? 1.0f : 0.0f;
        part[q * 128 + col] = c;
        __syncthreads();
        if (t < 128) {
            float s = part[t] + part[128 + t] + part[256 + t] + part[384 + t];
            __stcg(&g_norm[bb2 * NN + t], (s == 0.0f) ? 1.0f : s);
        }
    }
    gbar();

    // ================= P1: adjT + edge stage + init embedding ==============
    {
        float* s_wee = s_xT;            // 512   (63x8 zero-padded)
        float* s_nf  = s_xT + 512;      // 1024  [j][8]
        float* s_wi  = s_xT + 1536;     // 512
        float* s_red = s_xT + 2048;     // 512
        float* s_c   = s_w;             // [128][PW], k=0..63 used
        float* s_esT = s_xT;            // [64][PX] later (aliases scratch)

        // fills
        for (int i = t; i < 4096; i += NT) {       // adjT (persistent)
            int r = i >> 7, j = i & 127;
            s_aT[j * PX + r] = ob[(r0 + r) * DD + ADJ_OFF + j];
        }
        if (t < 512) s_wee[t] = (t < 504) ? W_ee[t] : 0.f;
        for (int i = t; i < 1024; i += NT) {
            int j = i >> 3, d = i & 7;
            s_nf[i] = (d < 7) ? ob[j * DD + d] : 0.f;
        }
        if (t < 512) {
            int f = t >> 3, d = t & 7;
            s_wi[t] = (d < 7) ? W_init[f * 7 + d] : 0.f;
        }
        if (t < 32) s_nm[t] = __ldcg(&g_norm[b * NN + r0 + t]);
        float mx = 0.f;
        for (int i = t; i < BB * NN; i += NT) mx = fmaxf(mx, __ldcg(&g_norm[i]));
        s_red[t] = mx;
        __syncthreads();
        for (int s = 256; s > 0; s >>= 1) {
            if (t < s) s_red[t] = fmaxf(s_red[t], s_red[t + s]);
            __syncthreads();
        }
        const float inv_max = 1.0f / s_red[0];

        // per-node edge constant c[j][k] = W_ee[k][1:8] . nf[j]
        for (int i = t; i < 8192; i += NT) {
            int j = i >> 6, k = i & 63;
            float c = 0.f;
            if (k < 63) {
                const float* w = s_wee + k * 8;
                const float* nf = s_nf + j * 8;
#pragma unroll
                for (int d = 0; d < 7; d++) c = fmaf(w[d + 1], nf[d], c);
            }
            s_c[j * PW + k] = c;
        }
        // init embedding (own 32 rows) -> g_cur
        for (int i = t; i < 2048; i += NT) {
            int r = i >> 6, f = i & 63;
            const float* w = s_wi + f * 8;
            const float* nf = s_nf + (r0 + r) * 8;
            float e = 0.f;
#pragma unroll
            for (int d = 0; d < 7; d++) e = fmaf(w[d], nf[d], e);
            __stcg(&g_cur[(b * NN + r0 + r) * 64 + f], fmaxf(e, 0.f));
        }
        __syncthreads();

        // edge sum: thread (r, f4-group); results stored transposed to esT
        {
            int r = t >> 4, eg = t & 15, f0 = eg << 2;
            float w0x = s_wee[(f0 + 0) * 8], w0y = s_wee[(f0 + 1) * 8];
            float w0z = s_wee[(f0 + 2) * 8], w0w = s_wee[(f0 + 3) * 8];
            float nrm = s_nm[r];
            __syncthreads();     // scratch (wee/nf/wi/red) dead; esT may alias
            float ax = 0.f, ay = 0.f, az = 0.f, aw = 0.f;
            const float* cp = s_c + f0;
            const float* ap = s_aT + r;
#pragma unroll 4
            for (int j = 0; j < NN; j++) {
                float a = ap[j * PX];
                if (a != 0.f) {
                    float4 c = *(const float4*)(cp + j * PW);
                    ax += fmaxf(fmaf(a, w0x, c.x), 0.f);
                    ay += fmaxf(fmaf(a, w0y, c.y), 0.f);
                    az += fmaxf(fmaf(a, w0z, c.z), 0.f);
                    aw += fmaxf(fmaf(a, w0w, c.w), 0.f);
                }
            }
            float inv = 1.0f / nrm;
            s_esT[(f0 + 0) * PX + r] = ax * inv;
            s_esT[(f0 + 1) * PX + r] = ay * inv;
            s_esT[(f0 + 2) * PX + r] = az * inv;
            s_esT[(f0 + 3) * PX + r] = (eg == 15) ? (nrm * inv_max) : aw * inv;
        }
        __syncthreads();

        // load W_ef transposed into s_w (overwrites c)
        for (int i = t; i < 4096; i += NT) {
            int f = i >> 6, k = i & 63;
            s_w[k * PW + f] = W_ef[i];
        }
        __syncthreads();

        // ee = relu(es @ W_ef^T) -> xT rows 64..127 (transposed)
        {
            float res[4][4];
            gemm32<16>(s_esT + kk * PX + rg * 4, s_w + kk * PW + fg * 4, res);
            if (kk == 0) {
#pragma unroll
                for (int e = 0; e < 4; e++) {
                    float4 v;
                    v.x = fmaxf(res[0][e], 0.f);
                    v.y = fmaxf(res[1][e], 0.f);
                    v.z = fmaxf(res[2][e], 0.f);
                    v.w = fmaxf(res[3][e], 0.f);
                    *(float4*)&s_xT[(64 + fg * 4 + e) * PX + rg * 4] = v;
                }
            }
        }
    }
    gbar();

    // ================= layers ==============================================
    for (int l = 0; l < 3; l++) {
        // full-batch cur -> s_w
        {
            const float4* gc = (const float4*)(g_cur + b * 8192);
            for (int i = t; i < 2048; i += NT) {
                float4 v = __ldcg(&gc[i]);
                int j = i >> 4, q = i & 15;
                *(float4*)&s_w[j * PW + q * 4] = v;
            }
        }
        __syncthreads();

        // S1: agg = adj @ cur / norm -> xT rows 0..63 (transposed)
        {
            float res[4][4];
            gemm32<32>(s_aT + kk * PX + rg * 4, s_w + kk * PW + fg * 4, res);
            if (kk == 0) {
                float i0 = 1.0f / s_nm[rg * 4 + 0];
                float i1 = 1.0f / s_nm[rg * 4 + 1];
                float i2 = 1.0f / s_nm[rg * 4 + 2];
                float i3 = 1.0f / s_nm[rg * 4 + 3];
#pragma unroll
                for (int e = 0; e < 4; e++) {
                    float4 v = make_float4(res[0][e] * i0, res[1][e] * i1,
                                           res[2][e] * i2, res[3][e] * i3);
                    *(float4*)&s_xT[(fg * 4 + e) * PX + rg * 4] = v;
                }
            }
        }
        // curT (own rows) -> cT rows 0..63  (reads s_w = cur, before overwrite)
        for (int i = t; i < 2048; i += NT) {
            int f = i >> 5, r = i & 31;
            s_cT[f * PX + r] = s_w[(r0 + r) * PW + f];
        }
        __syncthreads();

        // s_w <- Wm^T
        {
            const float4* gw = (const float4*)(g_Wt + (l * 2) * 8192);
            for (int i = t; i < 2048; i += NT) {
                float4 v = __ldcg(&gw[i]);
                int k = i >> 4, q = i & 15;
                *(float4*)&s_w[k * PW + q * 4] = v;
            }
        }
        __syncthreads();

        // S2: msg = relu([agg|ee] @ Wm^T) -> cT rows 64..127 (transposed)
        {
            float res[4][4];
            gemm32<32>(s_xT + kk * PX + rg * 4, s_w + kk * PW + fg * 4, res);
            __syncthreads();   // s_w reads done before reload below
            if (kk == 0) {
#pragma unroll
                for (int e = 0; e < 4; e++) {
                    float4 v;
                    v.x = fmaxf(res[0][e], 0.f);
                    v.y = fmaxf(res[1][e], 0.f);
                    v.z = fmaxf(res[2][e], 0.f);
                    v.w = fmaxf(res[3][e], 0.f);
                    *(float4*)&s_cT[(64 + fg * 4 + e) * PX + rg * 4] = v;
                }
            }
        }
        // s_w <- Wu^T
        {
            const float4* gw = (const float4*)(g_Wt + (l * 2 + 1) * 8192);
            for (int i = t; i < 2048; i += NT) {
                float4 v = __ldcg(&gw[i]);
                int k = i >> 4, q = i & 15;
                *(float4*)&s_w[k * PW + q * 4] = v;
            }
        }
        __syncthreads();

        // S3: cur' = relu([cur|msg] @ Wu^T) -> g_cur
        {
            float res[4][4];
            gemm32<32>(s_cT + kk * PX + rg * 4, s_w + kk * PW + fg * 4, res);
            if (kk == 0) {
#pragma unroll
                for (int q = 0; q < 4; q++) {
                    float4 o;
                    o.x = fmaxf(res[q][0], 0.f);
                    o.y = fmaxf(res[q][1], 0.f);
                    o.z = fmaxf(res[q][2], 0.f);
                    o.w = fmaxf(res[q][3], 0.f);
                    __stcg((float4*)&g_cur[(b * NN + r0 + rg * 4 + q) * 64 + fg * 4], o);
                }
            }
        }
        gbar();
    }

    // ================= P4: pooling + readout precompute ====================
    if (bid < 32) {
        float* s_cur  = sm;            // [128][64]
        float* s_part = sm + 8192;     // [8][64]
        float* s_pool = sm + 8704;     // 64
        float* s_rhp  = sm + 8768;     // 64
        const float4* gc = (const float4*)(g_cur + bid * 8192);
        for (int i = t; i < 2048; i += NT)
            *(float4*)&s_cur[i * 4] = __ldcg(&gc[i]);
        __syncthreads();
        {
            int f = t & 63, g = t >> 6;
            float s = 0.f;
            for (int i = g * 16; i < g * 16 + 16; i++) s += s_cur[i * 64 + f];
            s_part[g * 64 + f] = s;
        }
        __syncthreads();
        if (t < 64) {
            float s = 0.f;
#pragma unroll
            for (int g = 0; g < 8; g++) s += s_part[g * 64 + t];
            s_pool[t] = s * (1.0f / 128.0f);
        }
        __syncthreads();
        if (t < 64) {
            float acc = 0.f;
            for (int g = 0; g < 64; g++) acc = fmaf(Wp[t * 64 + g], s_pool[g], acc);
            s_rhp[t] = fmaxf(acc, 0.f);
        }
        __syncthreads();
        if (t < 4) {
            float acc = br[t];
            for (int f = 0; f < 64; f++) acc = fmaf(Wr[t * 192 + f], s_rhp[f], acc);
            __stcg(&g_Abias[bid * 4 + t], acc);
        }
        for (int o = t; o < 1024; o += NT) {
            int i = o >> 3, c = o & 7, oo = c & 3;
            const float* w = Wr + oo * 192 + ((c >= 4) ? 128 : 64);
            const float* cu = s_cur + i * 64;
            float acc = 0.f;
#pragma unroll 8
            for (int f = 0; f < 64; f++) acc = fmaf(w[f], cu[f], acc);
            __stcg(&g_PQ[(bid * NN + i) * 8 + c], acc);
        }
    }
    gbar();

    // ================= P5: broadcast readout write =========================
    {
        float4* sQ = (float4*)sm;          // 128
        float4* sP = sQ + 128;             // 32
        if (t < 128) sQ[t] = __ldcg((const float4*)&g_PQ[(b * NN + t) * 8 + 4]);
        else if (t < 160) sP[t - 128] = __ldcg((const float4*)&g_PQ[(b * NN + r0 + (t - 128)) * 8]);
        __syncthreads();
        float4 A = __ldcg((const float4*)&g_Abias[b * 4]);
        int i = r0 + (t >> 4), j0 = (t & 15) << 3;
        float4 P = sP[t >> 4];
        float px = A.x + P.x, py = A.y + P.y, pz = A.z + P.z, pw = A.w + P.w;
        float4* op = out + ((b * NN + i) * NN + j0);
#pragma unroll
        for (int j = 0; j < 8; j++) {
            float4 Q = sQ[j0 + j];
            op[j] = make_float4(px + Q.x, py + Q.y, pz + Q.z, pw + Q.w);
        }
    }
}

// ---------------- host launcher --------------------------------------------
extern "C" void kernel_launch(void* const* d_in, const int* in_sizes, int n_in,
                              void* d_out, int out_size) {
    const float* obs    = (const float*)d_in[0];
    const float* W_init = (const float*)d_in[1];
    const float* W_ee   = (const float*)d_in[2];
    const float* W_ef   = (const float*)d_in[3];
    const float* W_msg  = (const float*)d_in[4];
    const float* W_upd  = (const float*)d_in[5];
    const float* W_pool = (const float*)d_in[6];
    const float* W_read = (const float*)d_in[7];
    const float* b_read = (const float*)d_in[8];

    cudaFuncSetAttribute(k_mpnn, cudaFuncAttributeMaxDynamicSharedMemorySize,
                         SMW * 4);
    k_mpnn<<<GRID, NT, SMW * 4>>>(obs, W_init, W_ee, W_ef,
                                  W_msg, W_upd, W_pool, W_read, b_read,
                                  (float4*)d_out);
}

// round 9
// speedup vs baseline: 1.3482x; 1.0722x over previous
#include <cuda_runtime.h>

#define BB 32
#define NN 128
#define DD 135
#define ADJ_OFF 7
#define GRID 256
#define NT 512

#define PX 20              // pitch of transposed [k][16-row] buffers
#define PW 68              // pitch of [k][64-col] buffers
#define OFF_AT 0           // adjT [128][PX] (persistent)
#define OFF_XT 2560        // x input  [128][PX] (agg rows 0-63, ee rows 64-127)
#define OFF_CT 5120        // upd input [128][PX] (curT 0-63, msgT 64-127)
#define OFF_W  7680        // [128][PW] weights / full-batch cur / edge-c
#define OFF_NM 16384       // 16 norms
#define SMW    16416

__device__ float g_norm[BB * NN];
__device__ float g_cur[BB * NN * 64];
__device__ float g_Wt[6 * 128 * 64];   // transposed W_msg/W_upd [m][k][f]
__device__ float g_PQ[BB * NN * 8];
__device__ float g_Abias[BB * 4];
__device__ unsigned g_cnt = 0, g_gen = 0;

__device__ __forceinline__ void gbar() {
    __threadfence();
    __syncthreads();
    if (threadIdx.x == 0) {
        volatile unsigned* vg = &g_gen;
        unsigned gen = *vg;
        unsigned a = atomicAdd(&g_cnt, 1u);
        if (a == GRID - 1) {
            atomicExch(&g_cnt, 0u);
            __threadfence();
            atomicAdd(&g_gen, 1u);
        } else {
            while (*vg == gen) __nanosleep(64);
        }
    }
    __threadfence();
    __syncthreads();
}

__device__ __forceinline__ float rsum8(float v) {
    v += __shfl_xor_sync(0xffffffffu, v, 1);
    v += __shfl_xor_sync(0xffffffffu, v, 2);
    v += __shfl_xor_sync(0xffffffffu, v, 4);
    return v;
}

// res[q][e] = sum_k xT[k][rg*4+q] * w[k][fg*4+e]; k-split 8 over lane bits 0-2.
// xp = &xT[kk*PX + rg*4], wp = &w[kk*PW + fg*4]
template <int NK>
__device__ __forceinline__ void gemm16(const float* xp, const float* wp,
                                       float res[4][4]) {
    float4 a0 = {0.f, 0.f, 0.f, 0.f}, a1 = a0, a2 = a0, a3 = a0;
#pragma unroll
    for (int i = 0; i < NK; i++) {
        float4 x = *(const float4*)xp;
        float4 w = *(const float4*)wp;
        a0.x = fmaf(x.x, w.x, a0.x); a0.y = fmaf(x.x, w.y, a0.y);
        a0.z = fmaf(x.x, w.z, a0.z); a0.w = fmaf(x.x, w.w, a0.w);
        a1.x = fmaf(x.y, w.x, a1.x); a1.y = fmaf(x.y, w.y, a1.y);
        a1.z = fmaf(x.y, w.z, a1.z); a1.w = fmaf(x.y, w.w, a1.w);
        a2.x = fmaf(x.z, w.x, a2.x); a2.y = fmaf(x.z, w.y, a2.y);
        a2.z = fmaf(x.z, w.z, a2.z); a2.w = fmaf(x.z, w.w, a2.w);
        a3.x = fmaf(x.w, w.x, a3.x); a3.y = fmaf(x.w, w.y, a3.y);
        a3.z = fmaf(x.w, w.z, a3.z); a3.w = fmaf(x.w, w.w, a3.w);
        xp += 8 * PX;
        wp += 8 * PW;
    }
    res[0][0] = rsum8(a0.x); res[0][1] = rsum8(a0.y);
    res[0][2] = rsum8(a0.z); res[0][3] = rsum8(a0.w);
    res[1][0] = rsum8(a1.x); res[1][1] = rsum8(a1.y);
    res[1][2] = rsum8(a1.z); res[1][3] = rsum8(a1.w);
    res[2][0] = rsum8(a2.x); res[2][1] = rsum8(a2.y);
    res[2][2] = rsum8(a2.z); res[2][3] = rsum8(a2.w);
    res[3][0] = rsum8(a3.x); res[3][1] = rsum8(a3.y);
    res[3][2] = rsum8(a3.z); res[3][3] = rsum8(a3.w);
}

__global__ __launch_bounds__(NT, 2)
void k_mpnn(const float* __restrict__ obs,
            const float* __restrict__ W_init,
            const float* __restrict__ W_ee,
            const float* __restrict__ W_ef,
            const float* __restrict__ Wm_g,
            const float* __restrict__ Wu_g,
            const float* __restrict__ Wp,
            const float* __restrict__ Wr,
            const float* __restrict__ br,
            float4* __restrict__ out) {
    extern __shared__ float sm[];
    const int t = threadIdx.x;
    const int bid = blockIdx.x;
    float* s_aT = sm + OFF_AT;
    float* s_xT = sm + OFF_XT;
    float* s_cT = sm + OFF_CT;
    float* s_w  = sm + OFF_W;
    float* s_nm = sm + OFF_NM;

    const int b  = bid >> 3;
    const int r0 = (bid & 7) << 4;          // 16-row chunk
    const float* ob = obs + b * NN * DD;

    // lane decomposition: kk(8) x fg(16) x rg(4)
    const int lane = t & 31, warp = t >> 5;
    const int kk = lane & 7;
    const int fg = ((warp & 3) << 2) | (lane >> 3);   // 0..15
    const int rg = warp >> 2;                          // 0..3

    // ================= P0: weight transpose + norms ========================
    if (bid < 6) {
        const float* src = (bid & 1) ? (Wu_g + (bid >> 1) * 8192)
                                     : (Wm_g + (bid >> 1) * 8192);
        float* dst = g_Wt + bid * 8192;
        for (int i = t; i < 8192; i += NT) {
            int f = i >> 7, k = i & 127;
            __stcg(&dst[k * 64 + f], src[i]);
        }
    } else if (bid < 38) {
        int bb2 = bid - 6;
        float* part = sm;                       // [4][128]
        int q = t >> 7, col = t & 127;
        const float* o = obs + bb2 * (NN * DD) + ADJ_OFF;
        float c = 0.f;
        for (int i = q * 32; i < q * 32 + 32; i++)
            c += (o[i * DD + col] != 0.0f) ? 1.0f : 0.0f;
        part[q * 128 + col] = c;
        __syncthreads();
        if (t < 128) {
            float s = part[t] + part[128 + t] + part[256 + t] + part[384 + t];
            __stcg(&g_norm[bb2 * NN + t], (s == 0.0f) ? 1.0f : s);
        }
    }
    gbar();

    // ================= P1: adjT + edge stage + init embedding ==============
    {
        float* s_wee = s_xT;            // [0..511]  63x8 zero-padded
        float* s_nf  = s_xT + 512;      // [512..1535]  [j][8]
        float* s_wi  = s_xT + 1536;     // [1536..2047]
        float* s_red = s_cT;            // 512 (cT dead in P1)
        float* s_c   = s_w;             // [128][PW], k=0..63 used
        float* s_esT = s_xT;            // [64][PX] after scratch dead

        for (int i = t; i < 2048; i += NT) {       // adjT (persistent, 16 rows)
            int r = i >> 7, j = i & 127;
            s_aT[j * PX + r] = ob[(r0 + r) * DD + ADJ_OFF + j];
        }
        if (t < 512) s_wee[t] = (t < 504) ? W_ee[t] : 0.f;
        for (int i = t; i < 1024; i += NT) {
            int j = i >> 3, d = i & 7;
            s_nf[i] = (d < 7) ? ob[j * DD + d] : 0.f;
        }
        if (t < 512) {
            int f = t >> 3, d = t & 7;
            s_wi[t] = (d < 7) ? W_init[f * 7 + d] : 0.f;
        }
        if (t < 16) s_nm[t] = __ldcg(&g_norm[b * NN + r0 + t]);
        float mx = 0.f;
        for (int i = t; i < BB * NN; i += NT) mx = fmaxf(mx, __ldcg(&g_norm[i]));
        s_red[t] = mx;
        __syncthreads();
        for (int s = 256; s > 0; s >>= 1) {
            if (t < s) s_red[t] = fmaxf(s_red[t], s_red[t + s]);
            __syncthreads();
        }
        const float inv_max = 1.0f / s_red[0];

        // per-node edge constant c[j][k] = W_ee[k][1:8] . nf[j]
        for (int i = t; i < 8192; i += NT) {
            int j = i >> 6, k = i & 63;
            float c = 0.f;
            if (k < 63) {
                const float* w = s_wee + k * 8;
                const float* nf = s_nf + j * 8;
#pragma unroll
                for (int d = 0; d < 7; d++) c = fmaf(w[d + 1], nf[d], c);
            }
            s_c[j * PW + k] = c;
        }
        // init embedding (own 16 rows) -> g_cur
        for (int i = t; i < 1024; i += NT) {
            int r = i >> 6, f = i & 63;
            const float* w = s_wi + f * 8;
            const float* nf = s_nf + (r0 + r) * 8;
            float e = 0.f;
#pragma unroll
            for (int d = 0; d < 7; d++) e = fmaf(w[d], nf[d], e);
            __stcg(&g_cur[(b * NN + r0 + r) * 64 + f], fmaxf(e, 0.f));
        }
        __syncthreads();

        // edge sum: warp = row, lane = 2-feature group; write esT transposed
        {
            int r = warp;                    // 0..15
            int f0 = lane << 1;              // 0,2,..62
            float w0a = s_wee[f0 * 8];
            float w0b = s_wee[(f0 + 1) * 8];
            float nrm = s_nm[r];
            __syncthreads();                 // scratch (wee/nf/wi) dead below
            float ax = 0.f, ay = 0.f;
            const float* cp = s_c + f0;
            const float* ap = s_aT + r;
#pragma unroll 4
            for (int j = 0; j < NN; j++) {
                float a = ap[j * PX];
                if (a != 0.f) {
                    float2 c = *(const float2*)(cp + j * PW);
                    ax += fmaxf(fmaf(a, w0a, c.x), 0.f);
                    ay += fmaxf(fmaf(a, w0b, c.y), 0.f);
                }
            }
            float inv = 1.0f / nrm;
            s_esT[f0 * PX + r] = ax * inv;
            s_esT[(f0 + 1) * PX + r] = (lane == 31) ? (nrm * inv_max) : ay * inv;
        }
        __syncthreads();

        // W_ef^T -> s_w (overwrites c)
        for (int i = t; i < 4096; i += NT) {
            int f = i >> 6, k = i & 63;
            s_w[k * PW + f] = W_ef[i];
        }
        __syncthreads();

        // ee = relu(es @ W_ef^T) -> xT rows 64..127 (transposed)
        {
            float res[4][4];
            gemm16<8>(s_esT + kk * PX + rg * 4, s_w + kk * PW + fg * 4, res);
            if (kk == 0) {
#pragma unroll
                for (int e = 0; e < 4; e++) {
                    float4 v;
                    v.x = fmaxf(res[0][e], 0.f);
                    v.y = fmaxf(res[1][e], 0.f);
                    v.z = fmaxf(res[2][e], 0.f);
                    v.w = fmaxf(res[3][e], 0.f);
                    *(float4*)&s_xT[(64 + fg * 4 + e) * PX + rg * 4] = v;
                }
            }
        }
    }
    gbar();

    // ================= layers ==============================================
    for (int l = 0; l < 3; l++) {
        // full-batch cur -> s_w
        {
            const float4* gc = (const float4*)(g_cur + b * 8192);
            for (int i = t; i < 2048; i += NT) {
                float4 v = __ldcg(&gc[i]);
                int j = i >> 4, q = i & 15;
                *(float4*)&s_w[j * PW + q * 4] = v;
            }
        }
        __syncthreads();

        // S1: agg = adj @ cur / norm -> xT rows 0..63 (transposed)
        {
            float res[4][4];
            gemm16<16>(s_aT + kk * PX + rg * 4, s_w + kk * PW + fg * 4, res);
            if (kk == 0) {
                float i0 = 1.0f / s_nm[rg * 4 + 0];
                float i1 = 1.0f / s_nm[rg * 4 + 1];
                float i2 = 1.0f / s_nm[rg * 4 + 2];
                float i3 = 1.0f / s_nm[rg * 4 + 3];
#pragma unroll
                for (int e = 0; e < 4; e++) {
                    float4 v = make_float4(res[0][e] * i0, res[1][e] * i1,
                                           res[2][e] * i2, res[3][e] * i3);
                    *(float4*)&s_xT[(fg * 4 + e) * PX + rg * 4] = v;
                }
            }
        }
        // curT (own 16 rows) -> cT rows 0..63 (reads s_w before overwrite)
        for (int i = t; i < 1024; i += NT) {
            int f = i >> 4, r = i & 15;
            s_cT[f * PX + r] = s_w[(r0 + r) * PW + f];
        }
        __syncthreads();

        // s_w <- Wm^T
        {
            const float4* gw = (const float4*)(g_Wt + (l * 2) * 8192);
            for (int i = t; i < 2048; i += NT) {
                float4 v = __ldcg(&gw[i]);
                int k = i >> 4, q = i & 15;
                *(float4*)&s_w[k * PW + q * 4] = v;
            }
        }
        __syncthreads();

        // S2: msg = relu([agg|ee] @ Wm^T) -> cT rows 64..127
        {
            float res[4][4];
            gemm16<16>(s_xT + kk * PX + rg * 4, s_w + kk * PW + fg * 4, res);
            __syncthreads();   // s_w reads done before reload below
            if (kk == 0) {
#pragma unroll
                for (int e = 0; e < 4; e++) {
                    float4 v;
                    v.x = fmaxf(res[0][e], 0.f);
                    v.y = fmaxf(res[1][e], 0.f);
                    v.z = fmaxf(res[2][e], 0.f);
                    v.w = fmaxf(res[3][e], 0.f);
                    *(float4*)&s_cT[(64 + fg * 4 + e) * PX + rg * 4] = v;
                }
            }
        }
        // s_w <- Wu^T
        {
            const float4* gw = (const float4*)(g_Wt + (l * 2 + 1) * 8192);
            for (int i = t; i < 2048; i += NT) {
                float4 v = __ldcg(&gw[i]);
                int k = i >> 4, q = i & 15;
                *(float4*)&s_w[k * PW + q * 4] = v;
            }
        }
        __syncthreads();

        // S3: cur' = relu([cur|msg] @ Wu^T) -> g_cur
        {
            float res[4][4];
            gemm16<16>(s_cT + kk * PX + rg * 4, s_w + kk * PW + fg * 4, res);
            if (kk == 0) {
#pragma unroll
                for (int q = 0; q < 4; q++) {
                    float4 o;
                    o.x = fmaxf(res[q][0], 0.f);
                    o.y = fmaxf(res[q][1], 0.f);
                    o.z = fmaxf(res[q][2], 0.f);
                    o.w = fmaxf(res[q][3], 0.f);
                    __stcg((float4*)&g_cur[(b * NN + r0 + rg * 4 + q) * 64 + fg * 4], o);
                }
            }
        }
        gbar();
    }

    // ================= P4: pooling + readout precompute ====================
    if (bid < 32) {
        float* s_cur  = sm;            // [128][64]
        float* s_part = sm + 8192;     // [8][64]
        float* s_pool = sm + 8704;     // 64
        float* s_rhp  = sm + 8768;     // 64
        const float4* gc = (const float4*)(g_cur + bid * 8192);
        for (int i = t; i < 2048; i += NT)
            *(float4*)&s_cur[i * 4] = __ldcg(&gc[i]);
        __syncthreads();
        {
            int f = t & 63, g = t >> 6;
            float s = 0.f;
            for (int i = g * 16; i < g * 16 + 16; i++) s += s_cur[i * 64 + f];
            s_part[g * 64 + f] = s;
        }
        __syncthreads();
        if (t < 64) {
            float s = 0.f;
#pragma unroll
            for (int g = 0; g < 8; g++) s += s_part[g * 64 + t];
            s_pool[t] = s * (1.0f / 128.0f);
        }
        __syncthreads();
        if (t < 64) {
            float acc = 0.f;
            for (int g = 0; g < 64; g++) acc = fmaf(Wp[t * 64 + g], s_pool[g], acc);
            s_rhp[t] = fmaxf(acc, 0.f);
        }
        __syncthreads();
        if (t < 4) {
            float acc = br[t];
            for (int f = 0; f < 64; f++) acc = fmaf(Wr[t * 192 + f], s_rhp[f], acc);
            __stcg(&g_Abias[bid * 4 + t], acc);
        }
        for (int o = t; o < 1024; o += NT) {
            int i = o >> 3, c = o & 7, oo = c & 3;
            const float* w = Wr + oo * 192 + ((c >= 4) ? 128 : 64);
            const float* cu = s_cur + i * 64;
            float acc = 0.f;
#pragma unroll 8
            for (int f = 0; f < 64; f++) acc = fmaf(w[f], cu[f], acc);
            __stcg(&g_PQ[(bid * NN + i) * 8 + c], acc);
        }
    }
    gbar();

    // ================= P5: broadcast readout write =========================
    {
        float4* sQ = (float4*)sm;          // 128
        float4* sP = sQ + 128;             // 16
        if (t < 128) sQ[t] = __ldcg((const float4*)&g_PQ[(b * NN + t) * 8 + 4]);
        else if (t < 144) sP[t - 128] = __ldcg((const float4*)&g_PQ[(b * NN + r0 + (t - 128)) * 8]);
        __syncthreads();
        float4 A = __ldcg((const float4*)&g_Abias[b * 4]);
        int i = r0 + (t >> 5), j0 = (t & 31) << 2;   // 4 consecutive j per thread
        float4 P = sP[t >> 5];
        float px = A.x + P.x, py = A.y + P.y, pz = A.z + P.z, pw = A.w + P.w;
        float4* op = out + ((b * NN + i) * NN + j0);
#pragma unroll
        for (int j = 0; j < 4; j++) {
            float4 Q = sQ[j0 + j];
            op[j] = make_float4(px + Q.x, py + Q.y, pz + Q.z, pw + Q.w);
        }
    }
}

// ---------------- host launcher --------------------------------------------
extern "C" void kernel_launch(void* const* d_in, const int* in_sizes, int n_in,
                              void* d_out, int out_size) {
    const float* obs    = (const float*)d_in[0];
    const float* W_init = (const float*)d_in[1];
    const float* W_ee   = (const float*)d_in[2];
    const float* W_ef   = (const float*)d_in[3];
    const float* W_msg  = (const float*)d_in[4];
    const float* W_upd  = (const float*)d_in[5];
    const float* W_pool = (const float*)d_in[6];
    const float* W_read = (const float*)d_in[7];
    const float* b_read = (const float*)d_in[8];

    cudaFuncSetAttribute(k_mpnn, cudaFuncAttributeMaxDynamicSharedMemorySize,
                         SMW * 4);
    k_mpnn<<<GRID, NT, SMW * 4>>>(obs, W_init, W_ee, W_ef,
                                  W_msg, W_upd, W_pool, W_read, b_read,
                                  (float4*)d_out);
}

// round 10
// speedup vs baseline: 1.5042x; 1.1156x over previous
#include <cuda_runtime.h>

#define BB 32
#define NN 128
#define DD 135
#define ADJ_OFF 7
#define GRID 256
#define NT 512

#define PX 20              // pitch of transposed [k][16-row] buffers
#define PW 68              // pitch of [k][64-col] buffers
#define OFF_AT 0           // adjT [128][PX] (persistent)
#define OFF_XT 2560        // x input  [128][PX] (agg rows 0-63, ee rows 64-127)
#define OFF_CT 5120        // upd input [128][PX] (curT 0-63, msgT 64-127) / scratch
#define OFF_W  7680        // [128][PW] weights / full-batch cur / edge-c
#define OFF_NM 16384       // 16 norms (persistent whole kernel)
#define SMW    16416

__device__ float g_cur[BB * NN * 64];
__device__ float g_Wt[6 * 128 * 64];     // transposed W_msg/W_upd [m][k][f]
__device__ float g_PQ[BB * NN * 8];
__device__ float g_part[BB * 8 * 64];    // pool partials per (b, chunk)
__device__ unsigned g_maxbits;           // bits of max norm (pos floats)
__device__ unsigned g_cnt = 0, g_gen = 0;

__device__ __forceinline__ void gbar() {
    __threadfence();
    __syncthreads();
    if (threadIdx.x == 0) {
        volatile unsigned* vg = &g_gen;
        unsigned gen = *vg;
        unsigned a = atomicAdd(&g_cnt, 1u);
        if (a == GRID - 1) {
            atomicExch(&g_cnt, 0u);
            __threadfence();
            atomicAdd(&g_gen, 1u);
        } else {
            while (*vg == gen) __nanosleep(64);
        }
    }
    __threadfence();
    __syncthreads();
}

__device__ __forceinline__ float rsum8(float v) {
    v += __shfl_xor_sync(0xffffffffu, v, 1);
    v += __shfl_xor_sync(0xffffffffu, v, 2);
    v += __shfl_xor_sync(0xffffffffu, v, 4);
    return v;
}

// res[q][e] = sum_k xT[k][rg*4+q] * w[k][fg*4+e]; k-split 8 over lane bits 0-2.
template <int NK>
__device__ __forceinline__ void gemm16(const float* xp, const float* wp,
                                       float res[4][4]) {
    float4 a0 = {0.f, 0.f, 0.f, 0.f}, a1 = a0, a2 = a0, a3 = a0;
#pragma unroll
    for (int i = 0; i < NK; i++) {
        float4 x = *(const float4*)xp;
        float4 w = *(const float4*)wp;
        a0.x = fmaf(x.x, w.x, a0.x); a0.y = fmaf(x.x, w.y, a0.y);
        a0.z = fmaf(x.x, w.z, a0.z); a0.w = fmaf(x.x, w.w, a0.w);
        a1.x = fmaf(x.y, w.x, a1.x); a1.y = fmaf(x.y, w.y, a1.y);
        a1.z = fmaf(x.y, w.z, a1.z); a1.w = fmaf(x.y, w.w, a1.w);
        a2.x = fmaf(x.z, w.x, a2.x); a2.y = fmaf(x.z, w.y, a2.y);
        a2.z = fmaf(x.z, w.z, a2.z); a2.w = fmaf(x.z, w.w, a2.w);
        a3.x = fmaf(x.w, w.x, a3.x); a3.y = fmaf(x.w, w.y, a3.y);
        a3.z = fmaf(x.w, w.z, a3.z); a3.w = fmaf(x.w, w.w, a3.w);
        xp += 8 * PX;
        wp += 8 * PW;
    }
    res[0][0] = rsum8(a0.x); res[0][1] = rsum8(a0.y);
    res[0][2] = rsum8(a0.z); res[0][3] = rsum8(a0.w);
    res[1][0] = rsum8(a1.x); res[1][1] = rsum8(a1.y);
    res[1][2] = rsum8(a1.z); res[1][3] = rsum8(a1.w);
    res[2][0] = rsum8(a2.x); res[2][1] = rsum8(a2.y);
    res[2][2] = rsum8(a2.z); res[2][3] = rsum8(a2.w);
    res[3][0] = rsum8(a3.x); res[3][1] = rsum8(a3.y);
    res[3][2] = rsum8(a3.z); res[3][3] = rsum8(a3.w);
}

__global__ __launch_bounds__(NT, 2)
void k_mpnn(const float* __restrict__ obs,
            const float* __restrict__ W_init,
            const float* __restrict__ W_ee,
            const float* __restrict__ W_ef,
            const float* __restrict__ Wm_g,
            const float* __restrict__ Wu_g,
            const float* __restrict__ Wp,
            const float* __restrict__ Wr,
            const float* __restrict__ br,
            float4* __restrict__ out) {
    extern __shared__ float sm[];
    const int t = threadIdx.x;
    const int bid = blockIdx.x;
    float* s_aT = sm + OFF_AT;
    float* s_xT = sm + OFF_XT;
    float* s_cT = sm + OFF_CT;
    float* s_w  = sm + OFF_W;
    float* s_nm = sm + OFF_NM;

    const int b  = bid >> 3;
    const int r0 = (bid & 7) << 4;          // 16-row / 16-col chunk
    const float* ob = obs + b * NN * DD;

    // lane decomposition: kk(8) x fg(16) x rg(4)
    const int lane = t & 31, warp = t >> 5;
    const int kk = lane & 7;
    const int fg = ((warp & 3) << 2) | (lane >> 3);   // 0..15
    const int rg = warp >> 2;                          // 0..3

    // ============ P0: own-chunk norms (all blocks) + weight transpose ======
    {
        // norms for columns r0..r0+15: count nonzeros over 128 rows
        float* part = sm;                   // [16][33] scratch (aT region)
        int c = t & 15, iq = t >> 4;        // 32 row-groups of 4
        const float* o = ob + ADJ_OFF + r0 + c;
        float s = 0.f;
#pragma unroll
        for (int i = iq * 4; i < iq * 4 + 4; i++)
            s += (o[i * DD] != 0.0f) ? 1.0f : 0.0f;
        part[c * 33 + iq] = s;
        __syncthreads();
        if (t < 16) {
            float cnt = 0.f;
#pragma unroll 8
            for (int q = 0; q < 32; q++) cnt += part[t * 33 + q];
            s_nm[t] = (cnt == 0.f) ? 1.0f : cnt;
        }
        __syncthreads();
        if (t == 0) {
            float mx = s_nm[0];
#pragma unroll
            for (int q = 1; q < 16; q++) mx = fmaxf(mx, s_nm[q]);
            atomicMax(&g_maxbits, __float_as_uint(mx));
        }
        // weight transpose spread over 48 blocks
        if (bid < 48) {
            int m = bid >> 3, seg = bid & 7;
            const float* src = (m & 1) ? (Wu_g + (m >> 1) * 8192)
                                       : (Wm_g + (m >> 1) * 8192);
            float* dst = g_Wt + m * 8192;
            for (int i = seg * 1024 + t; i < seg * 1024 + 1024; i += NT) {
                int f = i >> 7, k = i & 127;
                __stcg(&dst[k * 64 + f], src[i]);
            }
        }
    }
    gbar();

    const float inv_max = 1.0f / __uint_as_float(__ldcg(&g_maxbits));

    // ============ P1: adjT + edge stage + init embedding ===================
    {
        float* s_wee = s_xT;            // [0..511]  63x8 zero-padded
        float* s_nf  = s_xT + 512;      // [512..1535]  [j][8]
        float* s_wi  = s_xT + 1536;     // [1536..2047]
        float* s_c   = s_w;             // [128][PW], k=0..63 used
        float* s_esT = s_xT;            // [64][PX] after scratch dead

        for (int i = t; i < 2048; i += NT) {       // adjT (persistent, 16 rows)
            int r = i >> 7, j = i & 127;
            s_aT[j * PX + r] = ob[(r0 + r) * DD + ADJ_OFF + j];
        }
        if (t < 512) s_wee[t] = (t < 504) ? W_ee[t] : 0.f;
        for (int i = t; i < 1024; i += NT) {
            int j = i >> 3, d = i & 7;
            s_nf[i] = (d < 7) ? ob[j * DD + d] : 0.f;
        }
        if (t < 512) {
            int f = t >> 3, d = t & 7;
            s_wi[t] = (d < 7) ? W_init[f * 7 + d] : 0.f;
        }
        __syncthreads();

        // per-node edge constant c[j][k] = W_ee[k][1:8] . nf[j]
        for (int i = t; i < 8192; i += NT) {
            int j = i >> 6, k = i & 63;
            float c = 0.f;
            if (k < 63) {
                const float* w = s_wee + k * 8;
                const float* nf = s_nf + j * 8;
#pragma unroll
                for (int d = 0; d < 7; d++) c = fmaf(w[d + 1], nf[d], c);
            }
            s_c[j * PW + k] = c;
        }
        // init embedding (own 16 rows) -> g_cur
        for (int i = t; i < 1024; i += NT) {
            int r = i >> 6, f = i & 63;
            const float* w = s_wi + f * 8;
            const float* nf = s_nf + (r0 + r) * 8;
            float e = 0.f;
#pragma unroll
            for (int d = 0; d < 7; d++) e = fmaf(w[d], nf[d], e);
            __stcg(&g_cur[(b * NN + r0 + r) * 64 + f], fmaxf(e, 0.f));
        }
        __syncthreads();

        // edge sum: warp = row, lane = 2-feature group; write esT transposed
        {
            int r = warp;                    // 0..15
            int f0 = lane << 1;              // 0,2,..62
            float w0a = s_wee[f0 * 8];
            float w0b = s_wee[(f0 + 1) * 8];
            float nrm = s_nm[r];
            __syncthreads();                 // scratch (wee/nf/wi) dead below
            float ax = 0.f, ay = 0.f;
            const float* cp = s_c + f0;
            const float* ap = s_aT + r;
#pragma unroll 4
            for (int j = 0; j < NN; j++) {
                float a = ap[j * PX];
                if (a != 0.f) {
                    float2 c = *(const float2*)(cp + j * PW);
                    ax += fmaxf(fmaf(a, w0a, c.x), 0.f);
                    ay += fmaxf(fmaf(a, w0b, c.y), 0.f);
                }
            }
            float inv = 1.0f / nrm;
            s_esT[f0 * PX + r] = ax * inv;
            s_esT[(f0 + 1) * PX + r] = (lane == 31) ? (nrm * inv_max) : ay * inv;
        }
        __syncthreads();

        // W_ef^T -> s_w (overwrites c)
        for (int i = t; i < 4096; i += NT) {
            int f = i >> 6, k = i & 63;
            s_w[k * PW + f] = W_ef[i];
        }
        __syncthreads();

        // ee = relu(es @ W_ef^T) -> xT rows 64..127 (transposed)
        {
            float res[4][4];
            gemm16<8>(s_esT + kk * PX + rg * 4, s_w + kk * PW + fg * 4, res);
            if (kk == 0) {
#pragma unroll
                for (int e = 0; e < 4; e++) {
                    float4 v;
                    v.x = fmaxf(res[0][e], 0.f);
                    v.y = fmaxf(res[1][e], 0.f);
                    v.z = fmaxf(res[2][e], 0.f);
                    v.w = fmaxf(res[3][e], 0.f);
                    *(float4*)&s_xT[(64 + fg * 4 + e) * PX + rg * 4] = v;
                }
            }
        }
    }
    gbar();

    // ============ layers ===================================================
    for (int l = 0; l < 3; l++) {
        // full-batch cur -> s_w
        {
            const float4* gc = (const float4*)(g_cur + b * 8192);
            for (int i = t; i < 2048; i += NT) {
                float4 v = __ldcg(&gc[i]);
                int j = i >> 4, q = i & 15;
                *(float4*)&s_w[j * PW + q * 4] = v;
            }
        }
        __syncthreads();

        // S1: agg = adj @ cur / norm -> xT rows 0..63 (transposed)
        {
            float res[4][4];
            gemm16<16>(s_aT + kk * PX + rg * 4, s_w + kk * PW + fg * 4, res);
            if (kk == 0) {
                float i0 = 1.0f / s_nm[rg * 4 + 0];
                float i1 = 1.0f / s_nm[rg * 4 + 1];
                float i2 = 1.0f / s_nm[rg * 4 + 2];
                float i3 = 1.0f / s_nm[rg * 4 + 3];
#pragma unroll
                for (int e = 0; e < 4; e++) {
                    float4 v = make_float4(res[0][e] * i0, res[1][e] * i1,
                                           res[2][e] * i2, res[3][e] * i3);
                    *(float4*)&s_xT[(fg * 4 + e) * PX + rg * 4] = v;
                }
            }
        }
        // curT (own 16 rows) -> cT rows 0..63 (reads s_w before overwrite)
        for (int i = t; i < 1024; i += NT) {
            int f = i >> 4, r = i & 15;
            s_cT[f * PX + r] = s_w[(r0 + r) * PW + f];
        }
        __syncthreads();

        // s_w <- Wm^T
        {
            const float4* gw = (const float4*)(g_Wt + (l * 2) * 8192);
            for (int i = t; i < 2048; i += NT) {
                float4 v = __ldcg(&gw[i]);
                int k = i >> 4, q = i & 15;
                *(float4*)&s_w[k * PW + q * 4] = v;
            }
        }
        __syncthreads();

        // S2: msg = relu([agg|ee] @ Wm^T) -> cT rows 64..127
        {
            float res[4][4];
            gemm16<16>(s_xT + kk * PX + rg * 4, s_w + kk * PW + fg * 4, res);
            __syncthreads();   // s_w reads done before reload below
            if (kk == 0) {
#pragma unroll
                for (int e = 0; e < 4; e++) {
                    float4 v;
                    v.x = fmaxf(res[0][e], 0.f);
                    v.y = fmaxf(res[1][e], 0.f);
                    v.z = fmaxf(res[2][e], 0.f);
                    v.w = fmaxf(res[3][e], 0.f);
                    *(float4*)&s_cT[(64 + fg * 4 + e) * PX + rg * 4] = v;
                }
            }
        }
        // s_w <- Wu^T
        {
            const float4* gw = (const float4*)(g_Wt + (l * 2 + 1) * 8192);
            for (int i = t; i < 2048; i += NT) {
                float4 v = __ldcg(&gw[i]);
                int k = i >> 4, q = i & 15;
                *(float4*)&s_w[k * PW + q * 4] = v;
            }
        }
        __syncthreads();

        // S3: cur' = relu([cur|msg] @ Wu^T)
        {
            float res[4][4];
            gemm16<16>(s_cT + kk * PX + rg * 4, s_w + kk * PW + fg * 4, res);
            if (l < 2) {
                if (kk == 0) {
#pragma unroll
                    for (int q = 0; q < 4; q++) {
                        float4 o;
                        o.x = fmaxf(res[q][0], 0.f);
                        o.y = fmaxf(res[q][1], 0.f);
                        o.z = fmaxf(res[q][2], 0.f);
                        o.w = fmaxf(res[q][3], 0.f);
                        __stcg((float4*)&g_cur[(b * NN + r0 + rg * 4 + q) * 64 + fg * 4], o);
                    }
                }
            } else {
                // final layer: keep cur' in smem (xT rows 0..63, transposed)
                if (kk == 0) {
#pragma unroll
                    for (int e = 0; e < 4; e++) {
                        float4 v;
                        v.x = fmaxf(res[0][e], 0.f);
                        v.y = fmaxf(res[1][e], 0.f);
                        v.z = fmaxf(res[2][e], 0.f);
                        v.w = fmaxf(res[3][e], 0.f);
                        *(float4*)&s_xT[(fg * 4 + e) * PX + rg * 4] = v;
                    }
                }
            }
        }
        if (l < 2) { gbar(); continue; }

        // ---- L3 tail: PQ + pool partials from smem cur' -------------------
        __syncthreads();
        {
            float* s_wr = s_cT;                 // [8][65]
            for (int i = t; i < 512; i += NT) {
                int c = i >> 6, f = i & 63;
                int oo = c & 3, base = (c >= 4) ? 128 : 64;
                s_wr[c * 65 + f] = Wr[oo * 192 + base + f];
            }
            __syncthreads();
            if (t < 128) {                      // PQ: thread = (i, c)
                int i = t >> 3, c = t & 7;
                float acc = 0.f;
#pragma unroll 8
                for (int f = 0; f < 64; f++)
                    acc = fmaf(s_wr[c * 65 + f], s_xT[f * PX + i], acc);
                __stcg(&g_PQ[(b * NN + r0 + i) * 8 + c], acc);
            } else if (t < 192) {               // pool partial: f = t-128
                int f = t - 128;
                float s = 0.f;
#pragma unroll
                for (int r = 0; r < 16; r++) s += s_xT[f * PX + r];
                __stcg(&g_part[(b * 8 + (bid & 7)) * 64 + f], s);
            }
        }
        gbar();
    }

    // ============ P5: pool reduce + Abias (redundant) + output =============
    {
        float* s_pool = s_cT;                  // 64
        float* s_rhp  = s_cT + 64;             // 64
        float* s_A    = s_cT + 128;            // 4
        if (t < 64) {
            float s = 0.f;
#pragma unroll
            for (int ch = 0; ch < 8; ch++)
                s += __ldcg(&g_part[(b * 8 + ch) * 64 + t]);
            s_pool[t] = s * (1.0f / 128.0f);
        }
        __syncthreads();
        if (t < 64) {
            float acc = 0.f;
#pragma unroll 8
            for (int g = 0; g < 64; g++) acc = fmaf(Wp[t * 64 + g], s_pool[g], acc);
            s_rhp[t] = fmaxf(acc, 0.f);
        }
        __syncthreads();
        if (t < 4) {
            float acc = br[t];
#pragma unroll 8
            for (int f = 0; f < 64; f++) acc = fmaf(Wr[t * 192 + f], s_rhp[f], acc);
            s_A[t] = acc;
        }
        float4* sQ = (float4*)sm;              // 128 (aT region dead)
        float4* sP = sQ + 128;                 // 16
        if (t < 128) sQ[t] = __ldcg((const float4*)&g_PQ[(b * NN + t) * 8 + 4]);
        else if (t < 144) sP[t - 128] = __ldcg((const float4*)&g_PQ[(b * NN + r0 + (t - 128)) * 8]);
        __syncthreads();
        float4 A = *(float4*)s_A;
        int i = r0 + (t >> 5), j0 = (t & 31) << 2;
        float4 P = sP[t >> 5];
        float px = A.x + P.x, py = A.y + P.y, pz = A.z + P.z, pw = A.w + P.w;
        float4* op = out + ((b * NN + i) * NN + j0);
#pragma unroll
        for (int j = 0; j < 4; j++) {
            float4 Q = sQ[j0 + j];
            op[j] = make_float4(px + Q.x, py + Q.y, pz + Q.z, pw + Q.w);
        }
    }
}

// ---------------- host launcher --------------------------------------------
extern "C" void kernel_launch(void* const* d_in, const int* in_sizes, int n_in,
                              void* d_out, int out_size) {
    const float* obs    = (const float*)d_in[0];
    const float* W_init = (const float*)d_in[1];
    const float* W_ee   = (const float*)d_in[2];
    const float* W_ef   = (const float*)d_in[3];
    const float* W_msg  = (const float*)d_in[4];
    const float* W_upd  = (const float*)d_in[5];
    const float* W_pool = (const float*)d_in[6];
    const float* W_read = (const float*)d_in[7];
    const float* b_read = (const float*)d_in[8];

    cudaFuncSetAttribute(k_mpnn, cudaFuncAttributeMaxDynamicSharedMemorySize,
                         SMW * 4);
    k_mpnn<<<GRID, NT, SMW * 4>>>(obs, W_init, W_ee, W_ef,
                                  W_msg, W_upd, W_pool, W_read, b_read,
                                  (float4*)d_out);
}

// round 11
// speedup vs baseline: 1.6157x; 1.0741x over previous
#include <cuda_runtime.h>

#define BB 32
#define NN 128
#define DD 135
#define ADJ_OFF 7
#define GRID 256
#define NT 512

#define PX 20              // pitch of transposed [k][16-row] buffers
#define PW 68              // pitch of [k][64-col] buffers
#define OFF_AT 0           // adjT [128][PX] (persistent)
#define OFF_XT 2560        // x input  [128][PX] (agg rows 0-63, ee rows 64-127)
#define OFF_CT 5120        // upd input [128][PX] (curT 0-63, msgT 64-127) / scratch
#define OFF_WA 7680        // buffer A [128][PW]: cur / Wu / edge-c / W_ef
#define OFF_WB 16384       // buffer B [128][PW]: Wm
#define OFF_NM 25088       // 16 norms (persistent)
#define SMW    25120

__device__ float g_cur[BB * NN * 64];
__device__ float g_Wt[6 * 128 * 64];     // transposed W_msg/W_upd [m][k][f]
__device__ float g_PQ[BB * NN * 8];
__device__ float g_part[BB * 8 * 64];    // pool partials per (b, chunk)
__device__ unsigned g_maxbits;           // bits of max norm (pos floats)
__device__ unsigned g_cnt = 0, g_gen = 0;

__device__ __forceinline__ void cp16(float* dst_smem, const void* src) {
    unsigned d = (unsigned)__cvta_generic_to_shared(dst_smem);
    asm volatile("cp.async.cg.shared.global [%0], [%1], 16;" :: "r"(d), "l"(src));
}
__device__ __forceinline__ void cp_wait_all() {
    asm volatile("cp.async.wait_all;" ::: "memory");
}

// fill [128][PW]-layout buffer from 2048 contiguous float4 (async)
__device__ __forceinline__ void fill_w_async(float* dst, const float* src, int t) {
    const float4* s = (const float4*)src;
#pragma unroll
    for (int q = 0; q < 4; q++) {
        int i = q * NT + t;
        int k = i >> 4, c = i & 15;
        cp16(&dst[k * PW + c * 4], &s[i]);
    }
}

__device__ __forceinline__ void gbar() {
    __threadfence();
    __syncthreads();
    if (threadIdx.x == 0) {
        volatile unsigned* vg = &g_gen;
        unsigned gen = *vg;
        unsigned a = atomicAdd(&g_cnt, 1u);
        if (a == GRID - 1) {
            atomicExch(&g_cnt, 0u);
            __threadfence();
            atomicAdd(&g_gen, 1u);
        } else {
            while (*vg == gen) __nanosleep(64);
        }
    }
    __threadfence();
    __syncthreads();
}

__device__ __forceinline__ float rsum8(float v) {
    v += __shfl_xor_sync(0xffffffffu, v, 1);
    v += __shfl_xor_sync(0xffffffffu, v, 2);
    v += __shfl_xor_sync(0xffffffffu, v, 4);
    return v;
}

// res[q][e] = sum_k xT[k][rg*4+q] * w[k][fg*4+e]; k-split 8 over lane bits 0-2.
template <int NK>
__device__ __forceinline__ void gemm16(const float* xp, const float* wp,
                                       float res[4][4]) {
    float4 a0 = {0.f, 0.f, 0.f, 0.f}, a1 = a0, a2 = a0, a3 = a0;
#pragma unroll
    for (int i = 0; i < NK; i++) {
        float4 x = *(const float4*)xp;
        float4 w = *(const float4*)wp;
        a0.x = fmaf(x.x, w.x, a0.x); a0.y = fmaf(x.x, w.y, a0.y);
        a0.z = fmaf(x.x, w.z, a0.z); a0.w = fmaf(x.x, w.w, a0.w);
        a1.x = fmaf(x.y, w.x, a1.x); a1.y = fmaf(x.y, w.y, a1.y);
        a1.z = fmaf(x.y, w.z, a1.z); a1.w = fmaf(x.y, w.w, a1.w);
        a2.x = fmaf(x.z, w.x, a2.x); a2.y = fmaf(x.z, w.y, a2.y);
        a2.z = fmaf(x.z, w.z, a2.z); a2.w = fmaf(x.z, w.w, a2.w);
        a3.x = fmaf(x.w, w.x, a3.x); a3.y = fmaf(x.w, w.y, a3.y);
        a3.z = fmaf(x.w, w.z, a3.z); a3.w = fmaf(x.w, w.w, a3.w);
        xp += 8 * PX;
        wp += 8 * PW;
    }
    res[0][0] = rsum8(a0.x); res[0][1] = rsum8(a0.y);
    res[0][2] = rsum8(a0.z); res[0][3] = rsum8(a0.w);
    res[1][0] = rsum8(a1.x); res[1][1] = rsum8(a1.y);
    res[1][2] = rsum8(a1.z); res[1][3] = rsum8(a1.w);
    res[2][0] = rsum8(a2.x); res[2][1] = rsum8(a2.y);
    res[2][2] = rsum8(a2.z); res[2][3] = rsum8(a2.w);
    res[3][0] = rsum8(a3.x); res[3][1] = rsum8(a3.y);
    res[3][2] = rsum8(a3.z); res[3][3] = rsum8(a3.w);
}

__global__ __launch_bounds__(NT, 2)
void k_mpnn(const float* __restrict__ obs,
            const float* __restrict__ W_init,
            const float* __restrict__ W_ee,
            const float* __restrict__ W_ef,
            const float* __restrict__ Wm_g,
            const float* __restrict__ Wu_g,
            const float* __restrict__ Wp,
            const float* __restrict__ Wr,
            const float* __restrict__ br,
            float4* __restrict__ out) {
    extern __shared__ float sm[];
    const int t = threadIdx.x;
    const int bid = blockIdx.x;
    float* s_aT = sm + OFF_AT;
    float* s_xT = sm + OFF_XT;
    float* s_cT = sm + OFF_CT;
    float* s_wa = sm + OFF_WA;
    float* s_wb = sm + OFF_WB;
    float* s_nm = sm + OFF_NM;

    const int b  = bid >> 3;
    const int r0 = (bid & 7) << 4;          // 16-row / 16-col chunk
    const float* ob = obs + b * NN * DD;

    // lane decomposition: kk(8) x fg(16) x rg(4)
    const int lane = t & 31, warp = t >> 5;
    const int kk = lane & 7;
    const int fg = ((warp & 3) << 2) | (lane >> 3);   // 0..15
    const int rg = warp >> 2;                          // 0..3

    // ============ P0: own-chunk norms (all blocks) + weight transpose ======
    {
        float* part = sm;                   // [16][33] scratch (aT region)
        int c = t & 15, iq = t >> 4;        // 32 row-groups of 4
        const float* o = ob + ADJ_OFF + r0 + c;
        float s = 0.f;
#pragma unroll
        for (int i = iq * 4; i < iq * 4 + 4; i++)
            s += (o[i * DD] != 0.0f) ? 1.0f : 0.0f;
        part[c * 33 + iq] = s;
        __syncthreads();
        if (t < 16) {
            float cnt = 0.f;
#pragma unroll 8
            for (int q = 0; q < 32; q++) cnt += part[t * 33 + q];
            s_nm[t] = (cnt == 0.f) ? 1.0f : cnt;
        }
        __syncthreads();
        if (t == 0) {
            float mx = s_nm[0];
#pragma unroll
            for (int q = 1; q < 16; q++) mx = fmaxf(mx, s_nm[q]);
            atomicMax(&g_maxbits, __float_as_uint(mx));
        }
        if (bid < 48) {
            int m = bid >> 3, seg = bid & 7;
            const float* src = (m & 1) ? (Wu_g + (m >> 1) * 8192)
                                       : (Wm_g + (m >> 1) * 8192);
            float* dst = g_Wt + m * 8192;
            for (int i = seg * 1024 + t; i < seg * 1024 + 1024; i += NT) {
                int f = i >> 7, k = i & 127;
                __stcg(&dst[k * 64 + f], src[i]);
            }
        }
    }
    gbar();

    const float inv_max = 1.0f / __uint_as_float(__ldcg(&g_maxbits));

    // prefetch Wm(layer 0) -> wB, hidden behind all of P1
    fill_w_async(s_wb, g_Wt, t);

    // ============ P1: adjT + edge stage + init embedding ===================
    {
        float* s_wee = s_xT;            // [0..511]  63x8 zero-padded
        float* s_nf  = s_xT + 512;      // [512..1535]  [j][8]
        float* s_wi  = s_xT + 1536;     // [1536..2047]
        float* s_c   = s_wa;            // [128][PW], k=0..63 used
        float* s_esT = s_xT;            // [64][PX] after scratch dead

        for (int i = t; i < 2048; i += NT) {       // adjT (persistent, 16 rows)
            int r = i >> 7, j = i & 127;
            s_aT[j * PX + r] = ob[(r0 + r) * DD + ADJ_OFF + j];
        }
        if (t < 512) s_wee[t] = (t < 504) ? W_ee[t] : 0.f;
        for (int i = t; i < 1024; i += NT) {
            int j = i >> 3, d = i & 7;
            s_nf[i] = (d < 7) ? ob[j * DD + d] : 0.f;
        }
        if (t < 512) {
            int f = t >> 3, d = t & 7;
            s_wi[t] = (d < 7) ? W_init[f * 7 + d] : 0.f;
        }
        __syncthreads();

        // per-node edge constant c[j][k] = W_ee[k][1:8] . nf[j]
        for (int i = t; i < 8192; i += NT) {
            int j = i >> 6, k = i & 63;
            float c = 0.f;
            if (k < 63) {
                const float* w = s_wee + k * 8;
                const float* nf = s_nf + j * 8;
#pragma unroll
                for (int d = 0; d < 7; d++) c = fmaf(w[d + 1], nf[d], c);
            }
            s_c[j * PW + k] = c;
        }
        // init embedding (own 16 rows) -> g_cur
        for (int i = t; i < 1024; i += NT) {
            int r = i >> 6, f = i & 63;
            const float* w = s_wi + f * 8;
            const float* nf = s_nf + (r0 + r) * 8;
            float e = 0.f;
#pragma unroll
            for (int d = 0; d < 7; d++) e = fmaf(w[d], nf[d], e);
            __stcg(&g_cur[(b * NN + r0 + r) * 64 + f], fmaxf(e, 0.f));
        }
        __syncthreads();

        // edge sum: warp = row, lane = 2-feature group; write esT transposed
        {
            int r = warp;                    // 0..15
            int f0 = lane << 1;              // 0,2,..62
            float w0a = s_wee[f0 * 8];
            float w0b = s_wee[(f0 + 1) * 8];
            float nrm = s_nm[r];
            __syncthreads();                 // scratch (wee/nf/wi) dead below
            float ax = 0.f, ay = 0.f;
            const float* cp = s_c + f0;
            const float* ap = s_aT + r;
#pragma unroll 4
            for (int j = 0; j < NN; j++) {
                float a = ap[j * PX];
                if (a != 0.f) {
                    float2 c = *(const float2*)(cp + j * PW);
                    ax += fmaxf(fmaf(a, w0a, c.x), 0.f);
                    ay += fmaxf(fmaf(a, w0b, c.y), 0.f);
                }
            }
            float inv = 1.0f / nrm;
            s_esT[f0 * PX + r] = ax * inv;
            s_esT[(f0 + 1) * PX + r] = (lane == 31) ? (nrm * inv_max) : ay * inv;
        }
        __syncthreads();

        // W_ef^T -> wA (overwrites c)
        for (int i = t; i < 4096; i += NT) {
            int f = i >> 6, k = i & 63;
            s_wa[k * PW + f] = W_ef[i];
        }
        __syncthreads();

        // ee = relu(es @ W_ef^T) -> xT rows 64..127 (transposed)
        {
            float res[4][4];
            gemm16<8>(s_esT + kk * PX + rg * 4, s_wa + kk * PW + fg * 4, res);
            if (kk == 0) {
#pragma unroll
                for (int e = 0; e < 4; e++) {
                    float4 v;
                    v.x = fmaxf(res[0][e], 0.f);
                    v.y = fmaxf(res[1][e], 0.f);
                    v.z = fmaxf(res[2][e], 0.f);
                    v.w = fmaxf(res[3][e], 0.f);
                    *(float4*)&s_xT[(64 + fg * 4 + e) * PX + rg * 4] = v;
                }
            }
        }
    }
    gbar();

    // ============ layers ===================================================
    for (int l = 0; l < 3; l++) {
        // cur -> wA (Wm for this layer already in wB via prefetch)
        fill_w_async(s_wa, g_cur + b * 8192, t);
        cp_wait_all();
        __syncthreads();                                   // sync#1

        // S1: agg = adj @ cur / norm -> xT rows 0..63 (transposed)
        {
            float res[4][4];
            gemm16<16>(s_aT + kk * PX + rg * 4, s_wa + kk * PW + fg * 4, res);
            if (kk == 0) {
                float i0 = 1.0f / s_nm[rg * 4 + 0];
                float i1 = 1.0f / s_nm[rg * 4 + 1];
                float i2 = 1.0f / s_nm[rg * 4 + 2];
                float i3 = 1.0f / s_nm[rg * 4 + 3];
#pragma unroll
                for (int e = 0; e < 4; e++) {
                    float4 v = make_float4(res[0][e] * i0, res[1][e] * i1,
                                           res[2][e] * i2, res[3][e] * i3);
                    *(float4*)&s_xT[(fg * 4 + e) * PX + rg * 4] = v;
                }
            }
        }
        // curT (own 16 rows) -> cT rows 0..63 (reads wA)
        for (int i = t; i < 1024; i += NT) {
            int f = i >> 4, r = i & 15;
            s_cT[f * PX + r] = s_wa[(r0 + r) * PW + f];
        }
        __syncthreads();                                   // sync#2

        // Wu -> wA (async, hidden behind S2 gemm)
        fill_w_async(s_wa, g_Wt + (l * 2 + 1) * 8192, t);

        // S2: msg = relu([agg|ee] @ Wm^T) -> cT rows 64..127
        {
            float res[4][4];
            gemm16<16>(s_xT + kk * PX + rg * 4, s_wb + kk * PW + fg * 4, res);
            cp_wait_all();
            if (kk == 0) {
#pragma unroll
                for (int e = 0; e < 4; e++) {
                    float4 v;
                    v.x = fmaxf(res[0][e], 0.f);
                    v.y = fmaxf(res[1][e], 0.f);
                    v.z = fmaxf(res[2][e], 0.f);
                    v.w = fmaxf(res[3][e], 0.f);
                    *(float4*)&s_cT[(64 + fg * 4 + e) * PX + rg * 4] = v;
                }
            }
        }
        __syncthreads();                                   // sync#3

        // next layer's Wm -> wB (async, hidden behind S3 gemm)
        if (l < 2) fill_w_async(s_wb, g_Wt + ((l + 1) * 2) * 8192, t);

        // S3: cur' = relu([cur|msg] @ Wu^T)
        {
            float res[4][4];
            gemm16<16>(s_cT + kk * PX + rg * 4, s_wa + kk * PW + fg * 4, res);
            if (l < 2) {
                if (kk == 0) {
#pragma unroll
                    for (int q = 0; q < 4; q++) {
                        float4 o;
                        o.x = fmaxf(res[q][0], 0.f);
                        o.y = fmaxf(res[q][1], 0.f);
                        o.z = fmaxf(res[q][2], 0.f);
                        o.w = fmaxf(res[q][3], 0.f);
                        __stcg((float4*)&g_cur[(b * NN + r0 + rg * 4 + q) * 64 + fg * 4], o);
                    }
                }
            } else {
                if (kk == 0) {
#pragma unroll
                    for (int e = 0; e < 4; e++) {
                        float4 v;
                        v.x = fmaxf(res[0][e], 0.f);
                        v.y = fmaxf(res[1][e], 0.f);
                        v.z = fmaxf(res[2][e], 0.f);
                        v.w = fmaxf(res[3][e], 0.f);
                        *(float4*)&s_xT[(fg * 4 + e) * PX + rg * 4] = v;
                    }
                }
            }
        }
        if (l < 2) { cp_wait_all(); gbar(); continue; }

        // ---- L3 tail: PQ + pool partials from smem cur' -------------------
        __syncthreads();
        {
            float* s_wr = s_cT;                 // [8][65]
            for (int i = t; i < 512; i += NT) {
                int c = i >> 6, f = i & 63;
                int oo = c & 3, base = (c >= 4) ? 128 : 64;
                s_wr[c * 65 + f] = Wr[oo * 192 + base + f];
            }
            __syncthreads();
            if (t < 128) {                      // PQ: thread = (i, c)
                int i = t >> 3, c = t & 7;
                float acc = 0.f;
#pragma unroll 8
                for (int f = 0; f < 64; f++)
                    acc = fmaf(s_wr[c * 65 + f], s_xT[f * PX + i], acc);
                __stcg(&g_PQ[(b * NN + r0 + i) * 8 + c], acc);
            } else if (t < 192) {               // pool partial: f = t-128
                int f = t - 128;
                float s = 0.f;
#pragma unroll
                for (int r = 0; r < 16; r++) s += s_xT[f * PX + r];
                __stcg(&g_part[(b * 8 + (bid & 7)) * 64 + f], s);
            }
        }
        gbar();
    }

    // ============ P5: pool reduce + Abias (redundant) + output =============
    {
        float4* sQ = (float4*)sm;              // 128 (aT region dead)
        float4* sP = sQ + 128;                 // 16
        if (t < 128) cp16((float*)&sQ[t], &g_PQ[(b * NN + t) * 8 + 4]);
        else if (t < 144) cp16((float*)&sP[t - 128], &g_PQ[(b * NN + r0 + (t - 128)) * 8]);

        float* s_pool = s_cT;                  // 64
        float* s_rhp  = s_cT + 64;             // 64
        float* s_A    = s_cT + 128;            // 4
        if (t < 64) {
            float s = 0.f;
#pragma unroll
            for (int ch = 0; ch < 8; ch++)
                s += __ldcg(&g_part[(b * 8 + ch) * 64 + t]);
            s_pool[t] = s * (1.0f / 128.0f);
        }
        __syncthreads();
        if (t < 64) {
            float acc = 0.f;
#pragma unroll 8
            for (int g = 0; g < 64; g++) acc = fmaf(Wp[t * 64 + g], s_pool[g], acc);
            s_rhp[t] = fmaxf(acc, 0.f);
        }
        __syncthreads();
        if (t < 4) {
            float acc = br[t];
#pragma unroll 8
            for (int f = 0; f < 64; f++) acc = fmaf(Wr[t * 192 + f], s_rhp[f], acc);
            s_A[t] = acc;
        }
        cp_wait_all();
        __syncthreads();
        float4 A = *(float4*)s_A;
        int i = r0 + (t >> 5), j0 = (t & 31) << 2;
        float4 P = sP[t >> 5];
        float px = A.x + P.x, py = A.y + P.y, pz = A.z + P.z, pw = A.w + P.w;
        float4* op = out + ((b * NN + i) * NN + j0);
#pragma unroll
        for (int j = 0; j < 4; j++) {
            float4 Q = sQ[j0 + j];
            op[j] = make_float4(px + Q.x, py + Q.y, pz + Q.z, pw + Q.w);
        }
    }
}

// ---------------- host launcher --------------------------------------------
extern "C" void kernel_launch(void* const* d_in, const int* in_sizes, int n_in,
                              void* d_out, int out_size) {
    const float* obs    = (const float*)d_in[0];
    const float* W_init = (const float*)d_in[1];
    const float* W_ee   = (const float*)d_in[2];
    const float* W_ef   = (const float*)d_in[3];
    const float* W_msg  = (const float*)d_in[4];
    const float* W_upd  = (const float*)d_in[5];
    const float* W_pool = (const float*)d_in[6];
    const float* W_read = (const float*)d_in[7];
    const float* b_read = (const float*)d_in[8];

    cudaFuncSetAttribute(k_mpnn, cudaFuncAttributeMaxDynamicSharedMemorySize,
                         SMW * 4);
    k_mpnn<<<GRID, NT, SMW * 4>>>(obs, W_init, W_ee, W_ef,
                                  W_msg, W_upd, W_pool, W_read, b_read,
                                  (float4*)d_out);
}